// round 7
// baseline (speedup 1.0000x reference)
#include <cuda_runtime.h>
#include <cstdint>

#define B_   8
#define N_   64
#define E_   256
#define L_   128
#define PITCH  132
#define WPITCH 68

// ---------------- device globals ----------------
__device__ float g_A   [512*128];
__device__ float g_C   [512*128];
__device__ float g_eenc[2048*128];
__device__ float g_gve [2*8*128];
__device__ float g_gvn [2*8*128];
__device__ float g_ee  [512*256*128];
__device__ float g_Wt  [11*128*128];
__device__ int   g_csr_off [8*65];
__device__ int   g_csr_edge[8*256];

__device__ __forceinline__ float lrelu(float v){ return v > 0.f ? v : 0.01f*v; }
__device__ __forceinline__ uint32_t smem_u32(const void* p){
    uint32_t a;
    asm("{ .reg .u64 t; cvta.to.shared.u64 t, %1; cvt.u32.u64 %0, t; }" : "=r"(a) : "l"(p));
    return a;
}
__device__ __forceinline__ float f2tf32f(float f){
    uint32_t r; asm("cvt.rna.tf32.f32 %0, %1;" : "=r"(r) : "f"(f));
    return __uint_as_float(r);
}
__device__ __forceinline__ float4 rnd4(float4 v){
    return make_float4(f2tf32f(v.x), f2tf32f(v.y), f2tf32f(v.z), f2tf32f(v.w));
}

#define LDSM4(D, addr) \
    asm volatile("ldmatrix.sync.aligned.m8n8.x4.shared.b16 {%0,%1,%2,%3}, [%4];" \
        : "=r"((D)[0]),"=r"((D)[1]),"=r"((D)[2]),"=r"((D)[3]) : "r"(addr))

#define MMA_T(C, A, b0, b1) \
    asm volatile("mma.sync.aligned.m16n8k8.row.col.f32.tf32.tf32.f32 " \
        "{%0,%1,%2,%3}, {%4,%5,%6,%7}, {%8,%9}, {%0,%1,%2,%3};" \
        : "+f"((C)[0]),"+f"((C)[1]),"+f"((C)[2]),"+f"((C)[3]) \
        : "r"((A)[0]),"r"((A)[1]),"r"((A)[2]),"r"((A)[3]), "r"(b0),"r"(b1))

// ---------------- gemm building blocks (A pre-rounded in smem; no cvt in loop) ----------------
template<int NT>
__device__ __forceinline__ void load_wchunk(float* s_w, const float* __restrict__ Wmat,
                                            int kc, int tid){
    const float* Wp = Wmat + kc;
    #pragma unroll
    for (int i = tid; i < 2048; i += NT){
        int n = i >> 4, k4 = i & 15;
        *(float4*)&s_w[n*WPITCH + k4*4] = *(const float4*)&Wp[n*128 + k4*4];
    }
}

// 16-warp 128x128: 2 B frags per warp
__device__ __forceinline__ void g128x16(float c[2][4][4], const uint32_t aA[2],
                                        const uint32_t aB[2], int kc){
    #pragma unroll
    for (int k = 0; k < 8; k++){
        uint32_t A[2][4];
        #pragma unroll
        for (int m = 0; m < 2; m++) LDSM4(A[m], aA[m] + (uint32_t)(kc + k*8)*4u);
        #pragma unroll
        for (int p = 0; p < 2; p++){
            uint32_t Bv[4];
            LDSM4(Bv, aB[p] + (uint32_t)k*32u);
            #pragma unroll
            for (int m = 0; m < 2; m++){
                MMA_T(c[m][2*p],   A[m], Bv[0], Bv[1]);
                MMA_T(c[m][2*p+1], A[m], Bv[2], Bv[3]);
            }
        }
    }
}

// 16-warp 64x128: 1 B frag per warp
__device__ __forceinline__ void g64x16(float c[2][2][4], const uint32_t aA[2],
                                       uint32_t aB, int kc){
    #pragma unroll
    for (int k = 0; k < 8; k++){
        uint32_t A[2][4];
        #pragma unroll
        for (int m = 0; m < 2; m++) LDSM4(A[m], aA[m] + (uint32_t)(kc + k*8)*4u);
        uint32_t Bv[4];
        LDSM4(Bv, aB + (uint32_t)k*32u);
        #pragma unroll
        for (int m = 0; m < 2; m++){
            MMA_T(c[m][0], A[m], Bv[0], Bv[1]);
            MMA_T(c[m][1], A[m], Bv[2], Bv[3]);
        }
    }
}

// ---------------- merged prep kernel ----------------
// blocks [0,22): weight transpose (2 per mat, coalesced via smem)
// [22,86): A/C gemm ; [86,94): csr ; [94,126): gvec
__global__ void k_prep(const float* __restrict__ x, const float* __restrict__ Wne,
                       const float* __restrict__ u, const float* __restrict__ Wg,
                       const float* __restrict__ bg,
                       const float* __restrict__ Wenc,
                       const float* __restrict__ Wedge, const float* __restrict__ be,
                       const float* __restrict__ Wnode, const float* __restrict__ bn,
                       const int* __restrict__ edge_index){
    __shared__ float sbuf[64*129];
    int blk = blockIdx.x, tid = threadIdx.x;
    if (blk < 22){
        // transpose mat = blk>>1, k-half = blk&1, coalesced both ways
        int mat = blk >> 1, k0 = (blk & 1)*64;
        int m = mat - 1, s = m / 5, t = m % 5;
        #pragma unroll
        for (int i = tid; i < 8192; i += 256){
            int kk = i >> 7, n = i & 127;
            int k = k0 + kk;
            float v;
            if (mat == 0) v = Wenc[k*L_ + n];
            else if (t == 0) v = Wedge[(s*512 +       k)*L_ + n];
            else if (t == 1) v = Wedge[(s*512 + 128 + k)*L_ + n];
            else if (t == 2) v = Wedge[(s*512 + 256 + k)*L_ + n];
            else if (t == 3) v = Wnode[(s*384 +       k)*L_ + n];
            else             v = Wnode[(s*384 + 128 + k)*L_ + n];
            sbuf[kk*129 + n] = v;
        }
        __syncthreads();
        #pragma unroll
        for (int j = tid; j < 8192; j += 256){
            int n = j >> 6, kk = j & 63;
            g_Wt[mat*16384 + n*128 + k0 + kk] = f2tf32f(sbuf[kk*129 + n]);
        }
    } else if (blk < 86){
        float (*xs)[128] = (float(*)[128])sbuf;
        const float* W1 = Wne;
        const float* W2 = Wne + 16384;
        int r0 = (blk - 22)*8;
        for (int i = tid; i < 1024; i += 256) xs[i>>7][i&127] = x[(r0 + (i>>7))*128 + (i&127)];
        __syncthreads();
        int c = tid & 127, rq = tid >> 7;
        float a1[4] = {0,0,0,0}, a2[4] = {0,0,0,0};
        for (int k = 0; k < 128; k++){
            float w1 = W1[k*128 + c], w2 = W2[k*128 + c];
            #pragma unroll
            for (int j = 0; j < 4; j++){
                float xv = xs[rq*4 + j][k];
                a1[j] += xv*w1; a2[j] += xv*w2;
            }
        }
        #pragma unroll
        for (int j = 0; j < 4; j++){
            g_A[(r0 + rq*4 + j)*128 + c] = a1[j];
            g_C[(r0 + rq*4 + j)*128 + c] = a2[j];
        }
    } else if (blk < 94){
        int* cnt = (int*)sbuf;
        int* off = cnt + 64;
        int b = blk - 86;
        if (tid < 64) cnt[tid] = 0;
        __syncthreads();
        int dv = edge_index[b*512 + 256 + tid];
        atomicAdd(&cnt[dv], 1);
        __syncthreads();
        if (tid == 0){
            int o = 0;
            for (int n = 0; n < 64; n++){ off[n] = o; o += cnt[n]; }
            off[64] = o;
            for (int n = 0; n <= 64; n++) g_csr_off[b*65 + n] = off[n];
            for (int n = 0; n < 64; n++) cnt[n] = off[n];
        }
        __syncthreads();
        int pos = atomicAdd(&cnt[dv], 1);
        g_csr_edge[b*256 + pos] = tid;
    } else {
        float* sgg = sbuf;
        int id = blk - 94;
        int b = id & 7, s = (id >> 3) & 1, kind = id >> 4;
        if (tid < 128){
            float acc = bg[tid];
            #pragma unroll 8
            for (int k = 0; k < 128; k++) acc += u[b*128 + k] * Wg[k*128 + tid];
            sgg[tid] = lrelu(acc);
        }
        __syncthreads();
        if (tid < 128){
            if (kind == 0){
                const float* W = Wedge + (s*512 + 384)*L_;
                float acc = be[s*128 + tid];
                #pragma unroll 8
                for (int k = 0; k < 128; k++) acc += sgg[k] * W[k*128 + tid];
                g_gve[(s*8 + b)*128 + tid] = acc;
            } else {
                const float* W = Wnode + (s*384 + 256)*L_;
                float acc = bn[s*128 + tid];
                #pragma unroll 8
                for (int k = 0; k < 128; k++) acc += sgg[k] * W[k*128 + tid];
                g_gvn[(s*8 + b)*128 + tid] = acc;
            }
        }
    }
}

// ---------------- edge encoder (uses g_Wt[0], 512 threads) ----------------
#define SMEM_EENC ((16896 + 8704 + 8704) * 4)
__global__ __launch_bounds__(512, 1) void k_eenc(const float* __restrict__ ea,
                                                 const float* __restrict__ bias){
    extern __shared__ float sm[];
    float* s_x  = sm;
    float* s_w  = sm + 16896;
    float* s_w2 = sm + 25600;
    int tid = threadIdx.x, wid = tid >> 5, lane = tid & 31;
    int row0 = blockIdx.x * 128;
    int trow = lane >> 2, tcol2 = (lane & 3)*2;
    int wr = (wid & 3)*32, wn = (wid >> 2)*32;

    #pragma unroll
    for (int i = tid; i < 4096; i += 512){
        int row = i >> 5, c4 = i & 31;
        float4 v = *(const float4*)&ea[(row0+row)*128 + c4*4];
        *(float4*)&s_x[row*PITCH + c4*4] = rnd4(v);
    }
    load_wchunk<512>(s_w,  g_Wt, 0,  tid);
    load_wchunk<512>(s_w2, g_Wt, 64, tid);
    __syncthreads();

    uint32_t xb = smem_u32(s_x), wb1 = smem_u32(s_w), wb2 = smem_u32(s_w2);
    uint32_t aA[2], aB[2], aB2[2];
    #pragma unroll
    for (int m = 0; m < 2; m++){
        int r = wr + m*16 + ((lane>>3)&1)*8 + (lane&7);
        aA[m] = xb + (uint32_t)(r*PITCH + ((lane>>4)<<2))*4u;
    }
    #pragma unroll
    for (int p = 0; p < 2; p++){
        int r = wn + p*16 + ((lane>>4)<<3) + (lane&7);
        uint32_t off = (uint32_t)(r*WPITCH + (((lane>>3)&1)<<2))*4u;
        aB[p] = wb1 + off; aB2[p] = wb2 + off;
    }
    float c8[2][4][4];
    #pragma unroll
    for (int m=0;m<2;m++) for (int nt=0;nt<4;nt++) for (int q=0;q<4;q++) c8[m][nt][q]=0.f;
    g128x16(c8, aA, aB, 0);
    g128x16(c8, aA, aB2, 64);

    #pragma unroll
    for (int m = 0; m < 2; m++){
        int rA = row0 + wr + m*16 + trow;
        #pragma unroll
        for (int nt = 0; nt < 4; nt++){
            int col = wn + nt*8 + tcol2;
            float2 bi = *(const float2*)&bias[col];
            *(float2*)&g_eenc[rA*128 + col] =
                make_float2(lrelu(c8[m][nt][0]+bi.x), lrelu(c8[m][nt][1]+bi.y));
            *(float2*)&g_eenc[(rA+8)*128 + col] =
                make_float2(lrelu(c8[m][nt][2]+bi.x), lrelu(c8[m][nt][3]+bi.y));
        }
    }
}

// ---------------- fused per-(b,d) kernel, 512 threads ----------------
#define O_X    0
#define O_W    16896
#define O_H    25600
#define O_HS   34048
#define O_HD   42496
#define O_GV   50944
#define O_WSC  51200
#define O_SC   51328
#define O_INT  51584
#define SMEM_FUSED ((51584 + 840) * 4)

__global__ __launch_bounds__(512, 1) void k_fused(
    const float* __restrict__ spdist, const int* __restrict__ edge_index,
    const float* __restrict__ w3, const float* __restrict__ bias,
    const float* __restrict__ Wsc, const float* __restrict__ bsc,
    float* __restrict__ out)
{
    extern __shared__ float sm[];
    float* s_x   = sm + O_X;
    float* s_w   = sm + O_W;
    float* s_h   = sm + O_H;
    float* s_hs  = sm + O_HS;
    float* s_hd  = sm + O_HD;
    float* s_gv  = sm + O_GV;
    float* s_wsc = sm + O_WSC;
    float* s_sc  = sm + O_SC;
    int*   s_src = (int*)(sm + O_INT);
    int*   s_dst = s_src + 256;
    int*   s_coff = s_dst + 256;
    int*   s_cedge = s_coff + 66;

    int tid = threadIdx.x, wid = tid >> 5, lane = tid & 31;
    int bd = blockIdx.x, b = bd >> 6, d = bd & 63;
    int trow = lane >> 2, tcol2 = (lane & 3)*2;
    int wr  = (wid & 3)*32, wn  = (wid >> 2)*32;
    int wr2 = (wid & 1)*32, wn2 = (wid >> 1)*16;
    float bsc0 = bsc[0];

    if (tid < 256){
        s_src[tid] = edge_index[b*512 + tid];
        s_dst[tid] = edge_index[b*512 + 256 + tid];
        s_cedge[tid] = g_csr_edge[b*256 + tid];
    }
    if (tid < 128) s_wsc[tid] = Wsc[tid];
    if (tid < 65)  s_coff[tid] = g_csr_off[b*65 + tid];

    // h0 = lrelu(A + C + sp*w3 + bias), rounded to tf32 (all consumers round anyway)
    #pragma unroll
    for (int i = tid; i < 2048; i += 512){
        int row = i >> 5, c4 = i & 31;
        float sp = spdist[(b*64 + d)*64 + row];
        float4 a  = *(const float4*)&g_A[(b*64 + row)*128 + c4*4];
        float4 cc = *(const float4*)&g_C[bd*128 + c4*4];
        float4 w  = *(const float4*)&w3[c4*4];
        float4 bi = *(const float4*)&bias[c4*4];
        float4 o;
        o.x = lrelu(a.x + cc.x + sp*w.x + bi.x);
        o.y = lrelu(a.y + cc.y + sp*w.y + bi.y);
        o.z = lrelu(a.z + cc.z + sp*w.z + bi.z);
        o.w = lrelu(a.w + cc.w + sp*w.w + bi.w);
        *(float4*)&s_h[row*PITCH + c4*4] = rnd4(o);
    }

    uint32_t xb = smem_u32(s_x), hb = smem_u32(s_h), gbm = smem_u32(s_hs), wsb = smem_u32(s_w);
    uint32_t aAx[2], aAh[2], aAg[2], aBw128[2];
    #pragma unroll
    for (int m = 0; m < 2; m++){
        int off = ((lane>>4)<<2);
        int rx = wr  + m*16 + ((lane>>3)&1)*8 + (lane&7);
        int rh = wr2 + m*16 + ((lane>>3)&1)*8 + (lane&7);
        aAx[m] = xb + (uint32_t)(rx*PITCH + off)*4u;
        aAh[m] = hb + (uint32_t)(rh*PITCH + off)*4u;
        aAg[m] = gbm + (uint32_t)(rh*PITCH + off)*4u;
    }
    #pragma unroll
    for (int p = 0; p < 2; p++){
        int r = wn + p*16 + ((lane>>4)<<3) + (lane&7);
        aBw128[p] = wsb + (uint32_t)(r*WPITCH + (((lane>>3)&1)<<2))*4u;
    }
    int nr2 = wn2 + ((lane>>4)<<3) + (lane&7);
    uint32_t kc4 = (uint32_t)((((lane>>3)&1)<<2));
    uint32_t aBw64 = wsb + (uint32_t)(nr2*WPITCH)*4u + kc4*4u;
    uint32_t aBx64 = xb  + (uint32_t)(nr2*WPITCH)*4u + kc4*4u;

    for (int s = 0; s < 2; s++){
        const float* Wbase = g_Wt + (1 + s*5)*16384;
        if (tid < 128) s_gv[tid] = g_gve[(s*8 + b)*128 + tid];
        else if (tid < 256 && s == 0) s_gv[tid] = g_gvn[b*128 + (tid - 128)];
        if (s == 1 && tid < 256) s_sc[tid] = bsc0;

        // ---- hs = h@Ws ; hd = h@Wd ---- (fp32 stores; epilogue-only consumers)
        for (int which = 0; which < 2; which++){
            const float* W = Wbase + (1 + which)*16384;
            __syncthreads();
            load_wchunk<512>(s_w, W, 0, tid);
            load_wchunk<512>(s_x, W, 64, tid);
            float c6[2][2][4];
            #pragma unroll
            for (int m=0;m<2;m++) for (int nt=0;nt<2;nt++) for (int q=0;q<4;q++) c6[m][nt][q]=0.f;
            __syncthreads();
            g64x16(c6, aAh, aBw64, 0);
            g64x16(c6, aAh, aBx64, 64);
            float* dstb = which ? s_hd : s_hs;
            #pragma unroll
            for (int m = 0; m < 2; m++){
                int rA = wr2 + m*16 + trow;
                #pragma unroll
                for (int nt = 0; nt < 2; nt++){
                    int col = wn2 + nt*8 + tcol2;
                    *(float2*)&dstb[rA*PITCH + col]     = make_float2(c6[m][nt][0], c6[m][nt][1]);
                    *(float2*)&dstb[(rA+8)*PITCH + col] = make_float2(c6[m][nt][2], c6[m][nt][3]);
                }
            }
        }

        // ---- edge tiles ----
        for (int et = 0; et < 2; et++){
            int e0 = et*128;
            __syncthreads();
            const float* Xsrc = (s == 0) ? (g_eenc + (b*256 + e0)*128)
                                         : (g_ee + (bd*256 + e0)*128);
            #pragma unroll
            for (int i = tid; i < 4096; i += 512){
                int row = i >> 5, c4 = i & 31;
                float4 v = *(const float4*)&Xsrc[row*128 + c4*4];
                *(float4*)&s_x[row*PITCH + c4*4] = rnd4(v);
            }
            load_wchunk<512>(s_w, Wbase, 0, tid);
            float c8[2][4][4];
            #pragma unroll
            for (int m=0;m<2;m++) for (int nt=0;nt<4;nt++) for (int q=0;q<4;q++) c8[m][nt][q]=0.f;
            __syncthreads();
            g128x16(c8, aAx, aBw128, 0);
            __syncthreads();
            load_wchunk<512>(s_w, Wbase, 64, tid);
            __syncthreads();
            g128x16(c8, aAx, aBw128, 64);

            if (s == 0){
                float* eeout = g_ee + (bd*256 + e0)*128;
                #pragma unroll
                for (int m = 0; m < 2; m++){
                    int lrA = wr + m*16 + trow, lrB = lrA + 8;
                    int sA = s_src[e0+lrA], dA = s_dst[e0+lrA];
                    int sB = s_src[e0+lrB], dB = s_dst[e0+lrB];
                    #pragma unroll
                    for (int nt = 0; nt < 4; nt++){
                        int col = wn + nt*8 + tcol2;
                        float2 gv = *(float2*)&s_gv[col];
                        float2 h1 = *(float2*)&s_hs[sA*PITCH + col];
                        float2 d1 = *(float2*)&s_hd[dA*PITCH + col];
                        float2 p1 = *(float2*)&s_x[lrA*PITCH + col];
                        *(float2*)&eeout[lrA*128 + col] = make_float2(
                            p1.x + lrelu(c8[m][nt][0] + h1.x + d1.x + gv.x),
                            p1.y + lrelu(c8[m][nt][1] + h1.y + d1.y + gv.y));
                        float2 h2 = *(float2*)&s_hs[sB*PITCH + col];
                        float2 d2 = *(float2*)&s_hd[dB*PITCH + col];
                        float2 p2 = *(float2*)&s_x[lrB*PITCH + col];
                        *(float2*)&eeout[lrB*128 + col] = make_float2(
                            p2.x + lrelu(c8[m][nt][2] + h2.x + d2.x + gv.x),
                            p2.y + lrelu(c8[m][nt][3] + h2.y + d2.y + gv.y));
                    }
                }
            } else {
                float part[2][2];
                part[0][0]=part[0][1]=part[1][0]=part[1][1]=0.f;
                #pragma unroll
                for (int m = 0; m < 2; m++){
                    int lrA = wr + m*16 + trow, lrB = lrA + 8;
                    int sA = s_src[e0+lrA], dA = s_dst[e0+lrA];
                    int sB = s_src[e0+lrB], dB = s_dst[e0+lrB];
                    #pragma unroll
                    for (int nt = 0; nt < 4; nt++){
                        int col = wn + nt*8 + tcol2;
                        float2 gv = *(float2*)&s_gv[col];
                        float2 wv = *(float2*)&s_wsc[col];
                        float2 h1 = *(float2*)&s_hs[sA*PITCH + col];
                        float2 d1 = *(float2*)&s_hd[dA*PITCH + col];
                        float2 p1 = *(float2*)&s_x[lrA*PITCH + col];
                        float o1x = p1.x + lrelu(c8[m][nt][0] + h1.x + d1.x + gv.x);
                        float o1y = p1.y + lrelu(c8[m][nt][1] + h1.y + d1.y + gv.y);
                        part[m][0] += o1x*wv.x + o1y*wv.y;
                        float2 h2 = *(float2*)&s_hs[sB*PITCH + col];
                        float2 d2 = *(float2*)&s_hd[dB*PITCH + col];
                        float2 p2 = *(float2*)&s_x[lrB*PITCH + col];
                        float o2x = p2.x + lrelu(c8[m][nt][2] + h2.x + d2.x + gv.x);
                        float o2y = p2.y + lrelu(c8[m][nt][3] + h2.y + d2.y + gv.y);
                        part[m][1] += o2x*wv.x + o2y*wv.y;
                    }
                }
                #pragma unroll
                for (int m = 0; m < 2; m++)
                    #pragma unroll
                    for (int i = 0; i < 2; i++){
                        float v = part[m][i];
                        v += __shfl_xor_sync(0xFFFFFFFFu, v, 1);
                        v += __shfl_xor_sync(0xFFFFFFFFu, v, 2);
                        if ((lane & 3) == 0)
                            atomicAdd(&s_sc[e0 + wr + m*16 + trow + i*8], v);
                    }
            }
        }

        if (s == 0){
            // ---- agg from g_ee (CSR), rounded (A operand of node gemm) ----
            __syncthreads();
            {
                int n = tid >> 3, cg = tid & 7;
                float acc[16];
                #pragma unroll
                for (int q = 0; q < 16; q++) acc[q] = 0.f;
                int j0 = s_coff[n], j1 = s_coff[n+1];
                const float* eb = g_ee + bd*256*128 + cg*16;
                for (int j = j0; j < j1; j++){
                    const float* p = eb + s_cedge[j]*128;
                    #pragma unroll
                    for (int q = 0; q < 4; q++){
                        float4 v = *(const float4*)&p[q*4];
                        acc[q*4]   += v.x; acc[q*4+1] += v.y;
                        acc[q*4+2] += v.z; acc[q*4+3] += v.w;
                    }
                }
                #pragma unroll
                for (int q = 0; q < 4; q++)
                    *(float4*)&s_hs[n*PITCH + cg*16 + q*4] =
                        rnd4(make_float4(acc[q*4], acc[q*4+1], acc[q*4+2], acc[q*4+3]));
            }
            const float* Wn1 = Wbase + 3*16384;
            const float* Wn2 = Wbase + 4*16384;
            load_wchunk<512>(s_w, Wn1, 0, tid);
            load_wchunk<512>(s_x, Wn1, 64, tid);
            float c6[2][2][4];
            #pragma unroll
            for (int m=0;m<2;m++) for (int nt=0;nt<2;nt++) for (int q=0;q<4;q++) c6[m][nt][q]=0.f;
            __syncthreads();
            g64x16(c6, aAh, aBw64, 0);
            g64x16(c6, aAh, aBx64, 64);
            __syncthreads();
            load_wchunk<512>(s_w, Wn2, 0, tid);
            load_wchunk<512>(s_x, Wn2, 64, tid);
            __syncthreads();
            g64x16(c6, aAg, aBw64, 0);
            g64x16(c6, aAg, aBx64, 64);
            __syncthreads();
            #pragma unroll
            for (int m = 0; m < 2; m++){
                int rA = wr2 + m*16 + trow;
                #pragma unroll
                for (int nt = 0; nt < 2; nt++){
                    int col = wn2 + nt*8 + tcol2;
                    float2 gv = *(float2*)&s_gv[128 + col];
                    float2 h1 = *(float2*)&s_h[rA*PITCH + col];
                    float2 h2 = *(float2*)&s_h[(rA+8)*PITCH + col];
                    h1.x = f2tf32f(h1.x + lrelu(c6[m][nt][0] + gv.x));
                    h1.y = f2tf32f(h1.y + lrelu(c6[m][nt][1] + gv.y));
                    h2.x = f2tf32f(h2.x + lrelu(c6[m][nt][2] + gv.x));
                    h2.y = f2tf32f(h2.y + lrelu(c6[m][nt][3] + gv.y));
                    *(float2*)&s_h[rA*PITCH + col]     = h1;
                    *(float2*)&s_h[(rA+8)*PITCH + col] = h2;
                }
            }
            __syncthreads();
        } else {
            __syncthreads();
            if (tid < 256)
                out[b*(E_*N_) + tid*N_ + d] = s_sc[tid];
        }
    }
}

// ---------------- launch ----------------
extern "C" void kernel_launch(void* const* d_in, const int* in_sizes, int n_in,
                              void* d_out, int out_size){
    const float* x          = (const float*)d_in[0];
    const float* edge_attr  = (const float*)d_in[1];
    const float* u          = (const float*)d_in[2];
    const float* spdist     = (const float*)d_in[3];
    const int*   edge_index = (const int*)  d_in[4];
    const float* W_node_enc = (const float*)d_in[5];
    const float* b_node_enc = (const float*)d_in[6];
    const float* W_edge_enc = (const float*)d_in[7];
    const float* b_edge_enc = (const float*)d_in[8];
    const float* W_glob_enc = (const float*)d_in[9];
    const float* b_glob_enc = (const float*)d_in[10];
    const float* W_edge_upd = (const float*)d_in[11];
    const float* b_edge_upd = (const float*)d_in[12];
    const float* W_node_upd = (const float*)d_in[13];
    const float* b_node_upd = (const float*)d_in[14];
    const float* W_score    = (const float*)d_in[15];
    const float* b_score    = (const float*)d_in[16];
    float* out = (float*)d_out;

    cudaFuncSetAttribute(k_eenc,  cudaFuncAttributeMaxDynamicSharedMemorySize, SMEM_EENC);
    cudaFuncSetAttribute(k_fused, cudaFuncAttributeMaxDynamicSharedMemorySize, SMEM_FUSED);

    k_prep <<<126, 256>>>(x, W_node_enc, u, W_glob_enc, b_glob_enc, W_edge_enc,
                          W_edge_upd, b_edge_upd, W_node_upd, b_node_upd, edge_index);
    k_eenc <<<16, 512, SMEM_EENC>>>(edge_attr, b_edge_enc);
    k_fused<<<512, 512, SMEM_FUSED>>>(spdist, edge_index,
                                      W_node_enc + 256*128, b_node_enc,
                                      W_score, b_score, out);
}

// round 8
// speedup vs baseline: 1.5258x; 1.5258x over previous
#include <cuda_runtime.h>
#include <cuda_fp16.h>
#include <cstdint>

#define B_   8
#define N_   64
#define E_   256
#define L_   128
#define PH    136      // half-element pitch for MMA operand tiles
#define PITCH 132      // float pitch for hs/hd tiles

// ---------------- device globals ----------------
__device__ float  g_A[512*128];
__device__ float  g_C[512*128];
__device__ __half g_eenc[2048*128];
__device__ float  g_gve[2*8*128];
__device__ float  g_gvn[2*8*128];
__device__ __half g_ee[512L*256*128];
__device__ __half g_Wh[11*128*128];       // pre-transposed [n][k] fp16 weights
__device__ int    g_csr_off[8*65];
__device__ int    g_csr_edge[8*256];

__device__ __forceinline__ float lrelu(float v){ return v > 0.f ? v : 0.01f*v; }
__device__ __forceinline__ uint32_t smem_u32(const void* p){
    uint32_t a;
    asm("{ .reg .u64 t; cvta.to.shared.u64 t, %1; cvt.u32.u64 %0, t; }" : "=r"(a) : "l"(p));
    return a;
}

#define LDSM4(D, addr) \
    asm volatile("ldmatrix.sync.aligned.m8n8.x4.shared.b16 {%0,%1,%2,%3}, [%4];" \
        : "=r"((D)[0]),"=r"((D)[1]),"=r"((D)[2]),"=r"((D)[3]) : "r"(addr))

#define MMA_H(C, A, b0, b1) \
    asm volatile("mma.sync.aligned.m16n8k16.row.col.f32.f16.f16.f32 " \
        "{%0,%1,%2,%3}, {%4,%5,%6,%7}, {%8,%9}, {%0,%1,%2,%3};" \
        : "+f"((C)[0]),"+f"((C)[1]),"+f"((C)[2]),"+f"((C)[3]) \
        : "r"((A)[0]),"r"((A)[1]),"r"((A)[2]),"r"((A)[3]), "r"(b0),"r"(b1))

// ---------------- tile copies (512 threads, 128x128 tiles) ----------------
__device__ __forceinline__ void copy_hh(__half* dst, const __half* __restrict__ src, int tid){
    #pragma unroll
    for (int i = tid; i < 2048; i += 512){
        int r = i >> 4, c = i & 15;
        *(uint4*)&dst[r*PH + c*8] = *(const uint4*)&src[r*128 + c*8];
    }
}
__device__ __forceinline__ void copy_f2h(__half* dst, const float* __restrict__ src, int tid){
    #pragma unroll
    for (int i = tid; i < 2048; i += 512){
        int r = i >> 4, c = i & 15;
        float4 v0 = *(const float4*)&src[r*128 + c*8];
        float4 v1 = *(const float4*)&src[r*128 + c*8 + 4];
        union { uint4 u; __half2 h[4]; } pk;
        pk.h[0] = __floats2half2_rn(v0.x, v0.y);
        pk.h[1] = __floats2half2_rn(v0.z, v0.w);
        pk.h[2] = __floats2half2_rn(v1.x, v1.y);
        pk.h[3] = __floats2half2_rn(v1.z, v1.w);
        *(uint4*)&dst[r*PH + c*8] = pk.u;
    }
}

// ---------------- gemm cores (fp16 in, fp32 accum) ----------------
// 128x128xK128, 16 warps (warp: 32m x 32n)
__device__ __forceinline__ void g128h(float c[2][4][4], const uint32_t aA[2], const uint32_t aB[2]){
    #pragma unroll
    for (int k = 0; k < 8; k++){
        uint32_t A0[4], A1[4];
        LDSM4(A0, aA[0] + (uint32_t)k*32u);
        LDSM4(A1, aA[1] + (uint32_t)k*32u);
        #pragma unroll
        for (int p = 0; p < 2; p++){
            uint32_t Bv[4];
            LDSM4(Bv, aB[p] + (uint32_t)k*32u);
            MMA_H(c[0][2*p],   A0, Bv[0], Bv[1]);
            MMA_H(c[0][2*p+1], A0, Bv[2], Bv[3]);
            MMA_H(c[1][2*p],   A1, Bv[0], Bv[1]);
            MMA_H(c[1][2*p+1], A1, Bv[2], Bv[3]);
        }
    }
}
// 64x128xK128, 16 warps (warp: 32m x 16n)
__device__ __forceinline__ void g64h(float c[2][2][4], const uint32_t aA[2], uint32_t aB){
    #pragma unroll
    for (int k = 0; k < 8; k++){
        uint32_t A0[4], A1[4], Bv[4];
        LDSM4(A0, aA[0] + (uint32_t)k*32u);
        LDSM4(A1, aA[1] + (uint32_t)k*32u);
        LDSM4(Bv, aB + (uint32_t)k*32u);
        MMA_H(c[0][0], A0, Bv[0], Bv[1]);
        MMA_H(c[0][1], A0, Bv[2], Bv[3]);
        MMA_H(c[1][0], A1, Bv[0], Bv[1]);
        MMA_H(c[1][1], A1, Bv[2], Bv[3]);
    }
}

// ---------------- merged prep kernel ----------------
// [0,22): weight transpose->fp16 ; [22,86): A/C gemm ; [86,94): csr ; [94,126): gvec
__global__ void k_prep(const float* __restrict__ x, const float* __restrict__ Wne,
                       const float* __restrict__ u, const float* __restrict__ Wg,
                       const float* __restrict__ bg,
                       const float* __restrict__ Wenc,
                       const float* __restrict__ Wedge, const float* __restrict__ be,
                       const float* __restrict__ Wnode, const float* __restrict__ bn,
                       const int* __restrict__ edge_index){
    __shared__ float sbuf[64*129];
    int blk = blockIdx.x, tid = threadIdx.x;
    if (blk < 22){
        int mat = blk >> 1, k0 = (blk & 1)*64;
        int m = mat - 1, s = m / 5, t = m % 5;
        #pragma unroll
        for (int i = tid; i < 8192; i += 256){
            int kk = i >> 7, n = i & 127;
            int k = k0 + kk;
            float v;
            if (mat == 0) v = Wenc[k*L_ + n];
            else if (t == 0) v = Wedge[(s*512 +       k)*L_ + n];
            else if (t == 1) v = Wedge[(s*512 + 128 + k)*L_ + n];
            else if (t == 2) v = Wedge[(s*512 + 256 + k)*L_ + n];
            else if (t == 3) v = Wnode[(s*384 +       k)*L_ + n];
            else             v = Wnode[(s*384 + 128 + k)*L_ + n];
            sbuf[kk*129 + n] = v;
        }
        __syncthreads();
        #pragma unroll
        for (int j = tid; j < 8192; j += 256){
            int n = j >> 6, kk = j & 63;
            g_Wh[mat*16384 + n*128 + k0 + kk] = __float2half_rn(sbuf[kk*129 + n]);
        }
    } else if (blk < 86){
        float (*xs)[128] = (float(*)[128])sbuf;
        const float* W1 = Wne;
        const float* W2 = Wne + 16384;
        int r0 = (blk - 22)*8;
        for (int i = tid; i < 1024; i += 256) xs[i>>7][i&127] = x[(r0 + (i>>7))*128 + (i&127)];
        __syncthreads();
        int c = tid & 127, rq = tid >> 7;
        float a1[4] = {0,0,0,0}, a2[4] = {0,0,0,0};
        #pragma unroll 4
        for (int k = 0; k < 128; k++){
            float w1 = W1[k*128 + c], w2 = W2[k*128 + c];
            #pragma unroll
            for (int j = 0; j < 4; j++){
                float xv = xs[rq*4 + j][k];
                a1[j] += xv*w1; a2[j] += xv*w2;
            }
        }
        #pragma unroll
        for (int j = 0; j < 4; j++){
            g_A[(r0 + rq*4 + j)*128 + c] = a1[j];
            g_C[(r0 + rq*4 + j)*128 + c] = a2[j];
        }
    } else if (blk < 94){
        int* cnt = (int*)sbuf;
        int* off = cnt + 64;
        int b = blk - 86;
        if (tid < 64) cnt[tid] = 0;
        __syncthreads();
        int dv = edge_index[b*512 + 256 + tid];
        atomicAdd(&cnt[dv], 1);
        __syncthreads();
        if (tid == 0){
            int o = 0;
            for (int n = 0; n < 64; n++){ off[n] = o; o += cnt[n]; }
            off[64] = o;
            for (int n = 0; n <= 64; n++) g_csr_off[b*65 + n] = off[n];
            for (int n = 0; n < 64; n++) cnt[n] = off[n];
        }
        __syncthreads();
        int pos = atomicAdd(&cnt[dv], 1);
        g_csr_edge[b*256 + pos] = tid;
    } else {
        float* sgg = sbuf;
        int id = blk - 94;
        int b = id & 7, s = (id >> 3) & 1, kind = id >> 4;
        if (tid < 128){
            float acc = bg[tid];
            #pragma unroll 8
            for (int k = 0; k < 128; k++) acc += u[b*128 + k] * Wg[k*128 + tid];
            sgg[tid] = lrelu(acc);
        }
        __syncthreads();
        if (tid < 128){
            if (kind == 0){
                const float* W = Wedge + (s*512 + 384)*L_;
                float acc = be[s*128 + tid];
                #pragma unroll 8
                for (int k = 0; k < 128; k++) acc += sgg[k] * W[k*128 + tid];
                g_gve[(s*8 + b)*128 + tid] = acc;
            } else {
                const float* W = Wnode + (s*384 + 256)*L_;
                float acc = bn[s*128 + tid];
                #pragma unroll 8
                for (int k = 0; k < 128; k++) acc += sgg[k] * W[k*128 + tid];
                g_gvn[(s*8 + b)*128 + tid] = acc;
            }
        }
    }
}

// ---------------- edge encoder ----------------
#define SMEM_EENC (34816*2)
__global__ __launch_bounds__(512, 1) void k_eenc(const float* __restrict__ ea,
                                                 const float* __restrict__ bias){
    extern __shared__ char smc[];
    __half* s_x = (__half*)smc;
    __half* s_w = (__half*)(smc + 34816);
    int tid = threadIdx.x, wid = tid >> 5, lane = tid & 31;
    int row0 = blockIdx.x * 128;
    int trow = lane >> 2, tcol2 = (lane & 3)*2;
    int wr = (wid & 3)*32, wn = (wid >> 2)*32;

    copy_f2h(s_x, ea + (long)row0*128, tid);
    copy_hh(s_w, g_Wh, tid);
    __syncthreads();

    uint32_t sb = smem_u32(smc);
    int l15 = lane & 15, kA = ((lane>>4)&1)*8, kB = ((lane>>3)&1)*8;
    uint32_t aA[2], aB[2];
    #pragma unroll
    for (int m = 0; m < 2; m++)
        aA[m] = sb + (uint32_t)(((wr + m*16 + l15)*PH + kA))*2u;
    #pragma unroll
    for (int p = 0; p < 2; p++){
        int rn = wn + p*16 + ((lane>>4)<<3) + (lane&7);
        aB[p] = sb + 34816u + (uint32_t)((rn*PH + kB))*2u;
    }
    float c8[2][4][4] = {};
    g128h(c8, aA, aB);

    #pragma unroll
    for (int m = 0; m < 2; m++){
        int rA = row0 + wr + m*16 + trow;
        #pragma unroll
        for (int nt = 0; nt < 4; nt++){
            int col = wn + nt*8 + tcol2;
            float2 bi = *(const float2*)&bias[col];
            *(__half2*)&g_eenc[(long)rA*128 + col] =
                __floats2half2_rn(lrelu(c8[m][nt][0]+bi.x), lrelu(c8[m][nt][1]+bi.y));
            *(__half2*)&g_eenc[(long)(rA+8)*128 + col] =
                __floats2half2_rn(lrelu(c8[m][nt][2]+bi.x), lrelu(c8[m][nt][3]+bi.y));
        }
    }
}

// ---------------- fused per-(b,d) kernel ----------------
// smem byte offsets
#define OB_X   0
#define OB_W   34816
#define OB_W2  69632
#define OB_H   104448
#define OB_AG  121856
#define OB_HS  139264
#define OB_HD  173056
#define OB_GV  206848
#define OB_WSC 207872
#define OB_SC  208384
#define OB_INT 209408
#define SMEM_FUSED (209408 + 834*4)

__global__ __launch_bounds__(512, 1) void k_fused(
    const float* __restrict__ spdist, const int* __restrict__ edge_index,
    const float* __restrict__ w3, const float* __restrict__ bias,
    const float* __restrict__ Wsc, const float* __restrict__ bsc,
    float* __restrict__ out)
{
    extern __shared__ char smc[];
    __half* s_x   = (__half*)(smc + OB_X);
    __half* s_w   = (__half*)(smc + OB_W);
    __half* s_w2  = (__half*)(smc + OB_W2);
    __half* s_h   = (__half*)(smc + OB_H);
    __half* s_ag  = (__half*)(smc + OB_AG);
    float*  s_hs  = (float*)(smc + OB_HS);
    float*  s_hd  = (float*)(smc + OB_HD);
    float*  s_gv  = (float*)(smc + OB_GV);
    float*  s_wsc = (float*)(smc + OB_WSC);
    float*  s_sc  = (float*)(smc + OB_SC);
    int*    s_src = (int*)(smc + OB_INT);
    int*    s_dst = s_src + 256;
    int*    s_coff = s_dst + 256;
    int*    s_cedge = s_coff + 66;

    int tid = threadIdx.x, wid = tid >> 5, lane = tid & 31;
    int bd = blockIdx.x, b = bd >> 6, d = bd & 63;
    int trow = lane >> 2, tcol2 = (lane & 3)*2;
    int wr  = (wid & 3)*32, wn  = (wid >> 2)*32;   // 128-row gemms
    int wr2 = (wid & 1)*32, wn2 = (wid >> 1)*16;   // 64-row gemms
    float bsc0 = bsc[0];

    if (tid < 256){
        s_src[tid] = edge_index[b*512 + tid];
        s_dst[tid] = edge_index[b*512 + 256 + tid];
        s_cedge[tid] = g_csr_edge[b*256 + tid];
    }
    if (tid < 128) s_wsc[tid] = Wsc[tid];
    if (tid < 65)  s_coff[tid] = g_csr_off[b*65 + tid];

    // h0 = lrelu(A + C + sp*w3 + bias) -> fp16
    #pragma unroll
    for (int i = tid; i < 2048; i += 512){
        int row = i >> 5, c4 = i & 31;
        float sp = spdist[(b*64 + d)*64 + row];
        float4 a  = *(const float4*)&g_A[(b*64 + row)*128 + c4*4];
        float4 cc = *(const float4*)&g_C[bd*128 + c4*4];
        float4 w  = *(const float4*)&w3[c4*4];
        float4 bi = *(const float4*)&bias[c4*4];
        union { uint2 u; __half2 h[2]; } pk;
        pk.h[0] = __floats2half2_rn(lrelu(a.x + cc.x + sp*w.x + bi.x),
                                    lrelu(a.y + cc.y + sp*w.y + bi.y));
        pk.h[1] = __floats2half2_rn(lrelu(a.z + cc.z + sp*w.z + bi.z),
                                    lrelu(a.w + cc.w + sp*w.w + bi.w));
        *(uint2*)&s_h[row*PH + c4*4] = pk.u;
    }

    // fragment addresses
    uint32_t sb = smem_u32(smc);
    int l15 = lane & 15, kA = ((lane>>4)&1)*8, kB = ((lane>>3)&1)*8;
    uint32_t aAx[2], aAh[2], aAg[2], aBe[2], aBs, aBs2;
    #pragma unroll
    for (int m = 0; m < 2; m++){
        aAx[m] = sb + OB_X  + (uint32_t)(((wr  + m*16 + l15)*PH + kA))*2u;
        aAh[m] = sb + OB_H  + (uint32_t)(((wr2 + m*16 + l15)*PH + kA))*2u;
        aAg[m] = sb + OB_AG + (uint32_t)(((wr2 + m*16 + l15)*PH + kA))*2u;
    }
    #pragma unroll
    for (int p = 0; p < 2; p++){
        int rn = wn + p*16 + ((lane>>4)<<3) + (lane&7);
        aBe[p] = sb + OB_W + (uint32_t)((rn*PH + kB))*2u;
    }
    {
        int rn = wn2 + ((lane>>4)<<3) + (lane&7);
        aBs  = sb + OB_W  + (uint32_t)((rn*PH + kB))*2u;
        aBs2 = sb + OB_W2 + (uint32_t)((rn*PH + kB))*2u;
    }

    for (int s = 0; s < 2; s++){
        const __half* Wb = g_Wh + (1 + s*5)*16384;
        if (tid < 128) s_gv[tid] = g_gve[(s*8 + b)*128 + tid];
        else if (tid < 256 && s == 0) s_gv[tid] = g_gvn[b*128 + (tid - 128)];
        if (s == 1 && tid < 256) s_sc[tid] = bsc0;
        __syncthreads();                       // prior users of s_w/s_w2 done; h0/updates visible
        copy_hh(s_w,  Wb + 1*16384, tid);      // Ws
        copy_hh(s_w2, Wb + 2*16384, tid);      // Wd
        __syncthreads();

        // hs = h@Ws -> s_hs (fp32); hd = h@Wd -> s_hd
        {
            float ch[2][2][4] = {};
            g64h(ch, aAh, aBs);
            #pragma unroll
            for (int m = 0; m < 2; m++){
                int rA = wr2 + m*16 + trow;
                #pragma unroll
                for (int nt = 0; nt < 2; nt++){
                    int col = wn2 + nt*8 + tcol2;
                    *(float2*)&s_hs[rA*PITCH + col]     = make_float2(ch[m][nt][0], ch[m][nt][1]);
                    *(float2*)&s_hs[(rA+8)*PITCH + col] = make_float2(ch[m][nt][2], ch[m][nt][3]);
                }
            }
        }
        {
            float cd[2][2][4] = {};
            g64h(cd, aAh, aBs2);
            #pragma unroll
            for (int m = 0; m < 2; m++){
                int rA = wr2 + m*16 + trow;
                #pragma unroll
                for (int nt = 0; nt < 2; nt++){
                    int col = wn2 + nt*8 + tcol2;
                    *(float2*)&s_hd[rA*PITCH + col]     = make_float2(cd[m][nt][0], cd[m][nt][1]);
                    *(float2*)&s_hd[(rA+8)*PITCH + col] = make_float2(cd[m][nt][2], cd[m][nt][3]);
                }
            }
        }
        __syncthreads();                       // hs/hd visible; s_w free
        copy_hh(s_w, Wb, tid);                 // Wedge (resident across both tiles)

        for (int et = 0; et < 2; et++){
            int e0 = et*128;
            if (et == 1) __syncthreads();      // tile0 s_x readers done
            const __half* Xsrc = (s == 0) ? (g_eenc + ((long)b*256 + e0)*128)
                                          : (g_ee + ((long)bd*256 + e0)*128);
            copy_hh(s_x, Xsrc, tid);
            __syncthreads();

            float c8[2][4][4] = {};
            g128h(c8, aAx, aBe);

            if (s == 0){
                __half* eeout = g_ee + ((long)bd*256 + e0)*128;
                #pragma unroll
                for (int m = 0; m < 2; m++){
                    int lrA = wr + m*16 + trow, lrB = lrA + 8;
                    int sA = s_src[e0+lrA], dA = s_dst[e0+lrA];
                    int sB = s_src[e0+lrB], dB = s_dst[e0+lrB];
                    #pragma unroll
                    for (int nt = 0; nt < 4; nt++){
                        int col = wn + nt*8 + tcol2;
                        float2 gv = *(float2*)&s_gv[col];
                        float2 h1 = *(float2*)&s_hs[sA*PITCH + col];
                        float2 d1 = *(float2*)&s_hd[dA*PITCH + col];
                        float2 p1 = __half22float2(*(__half2*)&s_x[lrA*PH + col]);
                        *(__half2*)&eeout[lrA*128 + col] = __floats2half2_rn(
                            p1.x + lrelu(c8[m][nt][0] + h1.x + d1.x + gv.x),
                            p1.y + lrelu(c8[m][nt][1] + h1.y + d1.y + gv.y));
                        float2 h2 = *(float2*)&s_hs[sB*PITCH + col];
                        float2 d2 = *(float2*)&s_hd[dB*PITCH + col];
                        float2 p2 = __half22float2(*(__half2*)&s_x[lrB*PH + col]);
                        *(__half2*)&eeout[lrB*128 + col] = __floats2half2_rn(
                            p2.x + lrelu(c8[m][nt][2] + h2.x + d2.x + gv.x),
                            p2.y + lrelu(c8[m][nt][3] + h2.y + d2.y + gv.y));
                    }
                }
            } else {
                float part[2][2] = {{0.f,0.f},{0.f,0.f}};
                #pragma unroll
                for (int m = 0; m < 2; m++){
                    int lrA = wr + m*16 + trow, lrB = lrA + 8;
                    int sA = s_src[e0+lrA], dA = s_dst[e0+lrA];
                    int sB = s_src[e0+lrB], dB = s_dst[e0+lrB];
                    #pragma unroll
                    for (int nt = 0; nt < 4; nt++){
                        int col = wn + nt*8 + tcol2;
                        float2 gv = *(float2*)&s_gv[col];
                        float2 wv = *(float2*)&s_wsc[col];
                        float2 h1 = *(float2*)&s_hs[sA*PITCH + col];
                        float2 d1 = *(float2*)&s_hd[dA*PITCH + col];
                        float2 p1 = __half22float2(*(__half2*)&s_x[lrA*PH + col]);
                        float o1x = p1.x + lrelu(c8[m][nt][0] + h1.x + d1.x + gv.x);
                        float o1y = p1.y + lrelu(c8[m][nt][1] + h1.y + d1.y + gv.y);
                        part[m][0] += o1x*wv.x + o1y*wv.y;
                        float2 h2 = *(float2*)&s_hs[sB*PITCH + col];
                        float2 d2 = *(float2*)&s_hd[dB*PITCH + col];
                        float2 p2 = __half22float2(*(__half2*)&s_x[lrB*PH + col]);
                        float o2x = p2.x + lrelu(c8[m][nt][2] + h2.x + d2.x + gv.x);
                        float o2y = p2.y + lrelu(c8[m][nt][3] + h2.y + d2.y + gv.y);
                        part[m][1] += o2x*wv.x + o2y*wv.y;
                    }
                }
                #pragma unroll
                for (int m = 0; m < 2; m++)
                    #pragma unroll
                    for (int i = 0; i < 2; i++){
                        float v = part[m][i];
                        v += __shfl_xor_sync(0xFFFFFFFFu, v, 1);
                        v += __shfl_xor_sync(0xFFFFFFFFu, v, 2);
                        if ((lane & 3) == 0)
                            atomicAdd(&s_sc[e0 + wr + m*16 + trow + i*8], v);
                    }
            }
        }
        __syncthreads();                       // g_ee / s_sc complete; s_w free

        if (s == 0){
            // agg from g_ee (CSR) -> s_ag (fp16); node weights into s_w/s_w2
            {
                int n = tid >> 3, cg = tid & 7;
                float acc[16];
                #pragma unroll
                for (int q = 0; q < 16; q++) acc[q] = 0.f;
                int j0 = s_coff[n], j1 = s_coff[n+1];
                const __half* eb = g_ee + (long)bd*32768 + cg*16;
                for (int j = j0; j < j1; j++){
                    const __half2* p = (const __half2*)(eb + s_cedge[j]*128);
                    #pragma unroll
                    for (int q = 0; q < 8; q++){
                        float2 v = __half22float2(p[q]);
                        acc[2*q] += v.x; acc[2*q+1] += v.y;
                    }
                }
                union { uint4 u[2]; __half2 h[8]; } pk;
                #pragma unroll
                for (int q = 0; q < 8; q++) pk.h[q] = __floats2half2_rn(acc[2*q], acc[2*q+1]);
                *(uint4*)&s_ag[n*PH + cg*16]     = pk.u[0];
                *(uint4*)&s_ag[n*PH + cg*16 + 8] = pk.u[1];
            }
            copy_hh(s_w,  Wb + 3*16384, tid);  // Wn1
            copy_hh(s_w2, Wb + 4*16384, tid);  // Wn2
            __syncthreads();

            float cn[2][2][4] = {};
            g64h(cn, aAh, aBs);                // h @ Wn1
            g64h(cn, aAg, aBs2);               // agg @ Wn2
            __syncthreads();                   // all s_h reads done
            #pragma unroll
            for (int m = 0; m < 2; m++){
                int rA = wr2 + m*16 + trow;
                #pragma unroll
                for (int nt = 0; nt < 2; nt++){
                    int col = wn2 + nt*8 + tcol2;
                    float2 gv = *(float2*)&s_gv[128 + col];
                    float2 h1 = __half22float2(*(__half2*)&s_h[rA*PH + col]);
                    float2 h2 = __half22float2(*(__half2*)&s_h[(rA+8)*PH + col]);
                    *(__half2*)&s_h[rA*PH + col] = __floats2half2_rn(
                        h1.x + lrelu(cn[m][nt][0] + gv.x),
                        h1.y + lrelu(cn[m][nt][1] + gv.y));
                    *(__half2*)&s_h[(rA+8)*PH + col] = __floats2half2_rn(
                        h2.x + lrelu(cn[m][nt][2] + gv.x),
                        h2.y + lrelu(cn[m][nt][3] + gv.y));
                }
            }
        } else {
            if (tid < 256)
                out[b*(E_*N_) + tid*N_ + d] = s_sc[tid];
        }
    }
}

// ---------------- launch ----------------
extern "C" void kernel_launch(void* const* d_in, const int* in_sizes, int n_in,
                              void* d_out, int out_size){
    const float* x          = (const float*)d_in[0];
    const float* edge_attr  = (const float*)d_in[1];
    const float* u          = (const float*)d_in[2];
    const float* spdist     = (const float*)d_in[3];
    const int*   edge_index = (const int*)  d_in[4];
    const float* W_node_enc = (const float*)d_in[5];
    const float* b_node_enc = (const float*)d_in[6];
    const float* W_edge_enc = (const float*)d_in[7];
    const float* b_edge_enc = (const float*)d_in[8];
    const float* W_glob_enc = (const float*)d_in[9];
    const float* b_glob_enc = (const float*)d_in[10];
    const float* W_edge_upd = (const float*)d_in[11];
    const float* b_edge_upd = (const float*)d_in[12];
    const float* W_node_upd = (const float*)d_in[13];
    const float* b_node_upd = (const float*)d_in[14];
    const float* W_score    = (const float*)d_in[15];
    const float* b_score    = (const float*)d_in[16];
    float* out = (float*)d_out;

    cudaFuncSetAttribute(k_eenc,  cudaFuncAttributeMaxDynamicSharedMemorySize, SMEM_EENC);
    cudaFuncSetAttribute(k_fused, cudaFuncAttributeMaxDynamicSharedMemorySize, SMEM_FUSED);

    k_prep <<<126, 256>>>(x, W_node_enc, u, W_glob_enc, b_glob_enc, W_edge_enc,
                          W_edge_upd, b_edge_upd, W_node_upd, b_node_upd, edge_index);
    k_eenc <<<16, 512, SMEM_EENC>>>(edge_attr, b_edge_enc);
    k_fused<<<512, 512, SMEM_FUSED>>>(spdist, edge_index,
                                      W_node_enc + 256*128, b_node_enc,
                                      W_score, b_score, out);
}

// round 9
// speedup vs baseline: 1.9793x; 1.2972x over previous
#include <cuda_runtime.h>
#include <cuda_fp16.h>
#include <cstdint>

#define B_   8
#define N_   64
#define E_   256
#define L_   128
#define PH    136      // half pitch for MMA operand tiles
#define PITCH 132      // float pitch for hs/hd tiles

// ---------------- device globals ----------------
__device__ float  g_A[512*128];
__device__ float  g_C[512*128];
__device__ __half g_eenc[2048*128];
__device__ float  g_gve[2*8*128];
__device__ float  g_gvn[2*8*128];
__device__ __half g_Wh[11*128*128];       // pre-transposed [n][k] fp16 weights
__device__ int    g_csr_off[8*65];
__device__ int    g_csr_edge[8*256];

__device__ __forceinline__ float lrelu(float v){ return v > 0.f ? v : 0.01f*v; }
__device__ __forceinline__ uint32_t smem_u32(const void* p){
    uint32_t a;
    asm("{ .reg .u64 t; cvta.to.shared.u64 t, %1; cvt.u32.u64 %0, t; }" : "=r"(a) : "l"(p));
    return a;
}

#define LDSM4(D, addr) \
    asm volatile("ldmatrix.sync.aligned.m8n8.x4.shared.b16 {%0,%1,%2,%3}, [%4];" \
        : "=r"((D)[0]),"=r"((D)[1]),"=r"((D)[2]),"=r"((D)[3]) : "r"(addr))

#define MMA_H(C, A, b0, b1) \
    asm volatile("mma.sync.aligned.m16n8k16.row.col.f32.f16.f16.f32 " \
        "{%0,%1,%2,%3}, {%4,%5,%6,%7}, {%8,%9}, {%0,%1,%2,%3};" \
        : "+f"((C)[0]),"+f"((C)[1]),"+f"((C)[2]),"+f"((C)[3]) \
        : "r"((A)[0]),"r"((A)[1]),"r"((A)[2]),"r"((A)[3]), "r"(b0),"r"(b1))

// ---------------- tile copies ----------------
template<int NT>
__device__ __forceinline__ void copy_hh(__half* dst, const __half* __restrict__ src, int tid){
    #pragma unroll
    for (int i = tid; i < 2048; i += NT){
        int r = i >> 4, c = i & 15;
        *(uint4*)&dst[r*PH + c*8] = *(const uint4*)&src[r*128 + c*8];
    }
}
template<int NT>
__device__ __forceinline__ void copy_f2h(__half* dst, const float* __restrict__ src, int tid){
    #pragma unroll
    for (int i = tid; i < 2048; i += NT){
        int r = i >> 4, c = i & 15;
        float4 v0 = *(const float4*)&src[r*128 + c*8];
        float4 v1 = *(const float4*)&src[r*128 + c*8 + 4];
        union { uint4 u; __half2 h[4]; } pk;
        pk.h[0] = __floats2half2_rn(v0.x, v0.y);
        pk.h[1] = __floats2half2_rn(v0.z, v0.w);
        pk.h[2] = __floats2half2_rn(v1.x, v1.y);
        pk.h[3] = __floats2half2_rn(v1.z, v1.w);
        *(uint4*)&dst[r*PH + c*8] = pk.u;
    }
}

// ---------------- gemm cores ----------------
// 128x128xK128, 16 warps (warp 32m x 32n)
__device__ __forceinline__ void g128h(float c[2][4][4], const uint32_t aA[2], const uint32_t aB[2]){
    #pragma unroll
    for (int k = 0; k < 8; k++){
        uint32_t A0[4], A1[4];
        LDSM4(A0, aA[0] + (uint32_t)k*32u);
        LDSM4(A1, aA[1] + (uint32_t)k*32u);
        #pragma unroll
        for (int p = 0; p < 2; p++){
            uint32_t Bv[4];
            LDSM4(Bv, aB[p] + (uint32_t)k*32u);
            MMA_H(c[0][2*p],   A0, Bv[0], Bv[1]);
            MMA_H(c[0][2*p+1], A0, Bv[2], Bv[3]);
            MMA_H(c[1][2*p],   A1, Bv[0], Bv[1]);
            MMA_H(c[1][2*p+1], A1, Bv[2], Bv[3]);
        }
    }
}
// 64x128xK128, 16 warps (warp 32m x 16n)
__device__ __forceinline__ void g64h(float c[2][2][4], const uint32_t aA[2], uint32_t aB){
    #pragma unroll
    for (int k = 0; k < 8; k++){
        uint32_t A0[4], A1[4], Bv[4];
        LDSM4(A0, aA[0] + (uint32_t)k*32u);
        LDSM4(A1, aA[1] + (uint32_t)k*32u);
        LDSM4(Bv, aB + (uint32_t)k*32u);
        MMA_H(c[0][0], A0, Bv[0], Bv[1]);
        MMA_H(c[0][1], A0, Bv[2], Bv[3]);
        MMA_H(c[1][0], A1, Bv[0], Bv[1]);
        MMA_H(c[1][1], A1, Bv[2], Bv[3]);
    }
}
// 128x128xK128, 8 warps (warp 32m x 64n) — for eenc blocks
__device__ __forceinline__ void g128h8(float c[2][8][4], const uint32_t aA[2], const uint32_t aB[4]){
    #pragma unroll
    for (int k = 0; k < 8; k++){
        uint32_t A0[4], A1[4];
        LDSM4(A0, aA[0] + (uint32_t)k*32u);
        LDSM4(A1, aA[1] + (uint32_t)k*32u);
        #pragma unroll
        for (int p = 0; p < 4; p++){
            uint32_t Bv[4];
            LDSM4(Bv, aB[p] + (uint32_t)k*32u);
            MMA_H(c[0][2*p],   A0, Bv[0], Bv[1]);
            MMA_H(c[0][2*p+1], A0, Bv[2], Bv[3]);
            MMA_H(c[1][2*p],   A1, Bv[0], Bv[1]);
            MMA_H(c[1][2*p+1], A1, Bv[2], Bv[3]);
        }
    }
}

// ---------------- merged prep kernel (256 threads) ----------------
// [0,22): weight transpose->fp16 ; [22,86): A/C gemm ; [86,94): csr ;
// [94,126): gvec (k-split) ; [126,142): edge encoder
#define SMEM_PREP (34816*2)
__global__ void k_prep(const float* __restrict__ x, const float* __restrict__ Wne,
                       const float* __restrict__ u, const float* __restrict__ Wg,
                       const float* __restrict__ bg,
                       const float* __restrict__ Wenc, const float* __restrict__ benc,
                       const float* __restrict__ ea,
                       const float* __restrict__ Wedge, const float* __restrict__ be,
                       const float* __restrict__ Wnode, const float* __restrict__ bn,
                       const int* __restrict__ edge_index){
    __shared__ float sbuf[64*129];
    extern __shared__ char dyn[];
    int blk = blockIdx.x, tid = threadIdx.x;
    if (blk < 22){
        int mat = blk >> 1, k0 = (blk & 1)*64;
        int m = mat - 1, s = m / 5, t = m % 5;
        #pragma unroll
        for (int i = tid; i < 8192; i += 256){
            int kk = i >> 7, n = i & 127;
            int k = k0 + kk;
            float v;
            if (mat == 0) v = Wenc[k*L_ + n];
            else if (t == 0) v = Wedge[(s*512 +       k)*L_ + n];
            else if (t == 1) v = Wedge[(s*512 + 128 + k)*L_ + n];
            else if (t == 2) v = Wedge[(s*512 + 256 + k)*L_ + n];
            else if (t == 3) v = Wnode[(s*384 +       k)*L_ + n];
            else             v = Wnode[(s*384 + 128 + k)*L_ + n];
            sbuf[kk*129 + n] = v;
        }
        __syncthreads();
        #pragma unroll
        for (int j = tid; j < 8192; j += 256){
            int n = j >> 6, kk = j & 63;
            g_Wh[mat*16384 + n*128 + k0 + kk] = __float2half_rn(sbuf[kk*129 + n]);
        }
    } else if (blk < 86){
        float (*xs)[128] = (float(*)[128])sbuf;
        const float* W1 = Wne;
        const float* W2 = Wne + 16384;
        int r0 = (blk - 22)*8;
        for (int i = tid; i < 1024; i += 256) xs[i>>7][i&127] = x[(r0 + (i>>7))*128 + (i&127)];
        __syncthreads();
        int c = tid & 127, rq = tid >> 7;
        float a1[4] = {0,0,0,0}, a2[4] = {0,0,0,0};
        #pragma unroll 8
        for (int k = 0; k < 128; k++){
            float w1 = W1[k*128 + c], w2 = W2[k*128 + c];
            #pragma unroll
            for (int j = 0; j < 4; j++){
                float xv = xs[rq*4 + j][k];
                a1[j] += xv*w1; a2[j] += xv*w2;
            }
        }
        #pragma unroll
        for (int j = 0; j < 4; j++){
            g_A[(r0 + rq*4 + j)*128 + c] = a1[j];
            g_C[(r0 + rq*4 + j)*128 + c] = a2[j];
        }
    } else if (blk < 94){
        int* cnt = (int*)sbuf;
        int* off = cnt + 64;
        int b = blk - 86;
        if (tid < 64) cnt[tid] = 0;
        __syncthreads();
        int dv = edge_index[b*512 + 256 + tid];
        atomicAdd(&cnt[dv], 1);
        __syncthreads();
        if (tid == 0){
            int o = 0;
            for (int n = 0; n < 64; n++){ off[n] = o; o += cnt[n]; }
            off[64] = o;
            for (int n = 0; n <= 64; n++) g_csr_off[b*65 + n] = off[n];
            for (int n = 0; n < 64; n++) cnt[n] = off[n];
        }
        __syncthreads();
        int pos = atomicAdd(&cnt[dv], 1);
        g_csr_edge[b*256 + pos] = tid;
    } else if (blk < 126){
        // gvec, 2-way k-split with smem reduce
        float* red = sbuf;          // 256
        float* sgg = sbuf + 256;    // 128
        int id = blk - 94;
        int b = id & 7, s = (id >> 3) & 1, kind = id >> 4;
        int c = tid & 127, hf = tid >> 7;
        float p = 0.f;
        #pragma unroll 16
        for (int k = 0; k < 64; k++)
            p += u[b*128 + hf*64 + k] * Wg[(hf*64 + k)*128 + c];
        red[tid] = p;
        __syncthreads();
        if (tid < 128) sgg[tid] = lrelu(bg[tid] + red[tid] + red[tid + 128]);
        __syncthreads();
        const float* W = (kind == 0) ? (Wedge + (s*512 + 384)*L_)
                                     : (Wnode + (s*384 + 256)*L_);
        float q = 0.f;
        #pragma unroll 16
        for (int k = 0; k < 64; k++)
            q += sgg[hf*64 + k] * W[(hf*64 + k)*128 + c];
        red[tid] = q;
        __syncthreads();
        if (tid < 128){
            float acc = ((kind == 0) ? be[s*128 + tid] : bn[s*128 + tid])
                      + red[tid] + red[tid + 128];
            if (kind == 0) g_gve[(s*8 + b)*128 + tid] = acc;
            else           g_gvn[(s*8 + b)*128 + tid] = acc;
        }
    } else {
        // edge encoder block (8 warps), local weight transpose
        __half* s_xh = (__half*)dyn;
        __half* s_wh = (__half*)(dyn + 34816);
        int eb = blk - 126;
        int row0 = eb*128;
        int wid = tid >> 5, lane = tid & 31;
        int trow = lane >> 2, tcol2 = (lane & 3)*2;
        int wr = (wid & 3)*32, wn = (wid >> 2)*64;

        copy_f2h<256>(s_xh, ea + (long)row0*128, tid);
        #pragma unroll
        for (int i = tid; i < 16384; i += 256){
            int k = i >> 7, n = i & 127;
            s_wh[n*PH + k] = __float2half_rn(Wenc[k*128 + n]);
        }
        __syncthreads();

        uint32_t sb = smem_u32(dyn);
        int l15 = lane & 15, kA = ((lane>>4)&1)*8, kB = ((lane>>3)&1)*8;
        uint32_t aA[2], aB[4];
        #pragma unroll
        for (int m = 0; m < 2; m++)
            aA[m] = sb + (uint32_t)(((wr + m*16 + l15)*PH + kA))*2u;
        #pragma unroll
        for (int p = 0; p < 4; p++){
            int rn = wn + p*16 + ((lane>>4)<<3) + (lane&7);
            aB[p] = sb + 34816u + (uint32_t)((rn*PH + kB))*2u;
        }
        float c8[2][8][4] = {};
        g128h8(c8, aA, aB);

        #pragma unroll
        for (int m = 0; m < 2; m++){
            int rA = row0 + wr + m*16 + trow;
            #pragma unroll
            for (int nt = 0; nt < 8; nt++){
                int col = wn + nt*8 + tcol2;
                float2 bi = *(const float2*)&benc[col];
                *(__half2*)&g_eenc[(long)rA*128 + col] =
                    __floats2half2_rn(lrelu(c8[m][nt][0]+bi.x), lrelu(c8[m][nt][1]+bi.y));
                *(__half2*)&g_eenc[(long)(rA+8)*128 + col] =
                    __floats2half2_rn(lrelu(c8[m][nt][2]+bi.x), lrelu(c8[m][nt][3]+bi.y));
            }
        }
    }
}

// ---------------- fused per-(b,d) kernel (ee fully SMEM-resident) ----------------
#define OB_EE  0         // 256 x PH fp16 = 69632 (two 128-row tiles, contiguous)
#define OB_W   69632     // 34816
#define OB_W2  104448    // 34816
#define OB_H   139264    // 17408
#define OB_HS  156672    // 33792 fp32  (s_ag fp16 aliases, 17408)
#define OB_HD  190464    // 33792 fp32
#define OB_GV  224256    // 2048 (gve s0 | gvn s0 | gve s1)
#define OB_WSC 226304    // 512
#define OB_SC  226816    // 1024
#define OB_INT 227840    // 3336
#define SMEM_FUSED 231176

__global__ __launch_bounds__(512, 1) void k_fused(
    const float* __restrict__ spdist, const int* __restrict__ edge_index,
    const float* __restrict__ w3, const float* __restrict__ bias,
    const float* __restrict__ Wsc, const float* __restrict__ bsc,
    float* __restrict__ out)
{
    extern __shared__ char smc[];
    __half* s_ee  = (__half*)(smc + OB_EE);
    __half* s_w   = (__half*)(smc + OB_W);
    __half* s_w2  = (__half*)(smc + OB_W2);
    __half* s_h   = (__half*)(smc + OB_H);
    __half* s_ag  = (__half*)(smc + OB_HS);     // aliases s_hs
    float*  s_hs  = (float*)(smc + OB_HS);
    float*  s_hd  = (float*)(smc + OB_HD);
    float*  s_gv  = (float*)(smc + OB_GV);
    float*  s_wsc = (float*)(smc + OB_WSC);
    float*  s_sc  = (float*)(smc + OB_SC);
    int*    s_src = (int*)(smc + OB_INT);
    int*    s_dst = s_src + 256;
    int*    s_coff = s_dst + 256;
    int*    s_cedge = s_coff + 66;

    int tid = threadIdx.x, wid = tid >> 5, lane = tid & 31;
    int bd = blockIdx.x, b = bd >> 6, d = bd & 63;
    int trow = lane >> 2, tcol2 = (lane & 3)*2;
    int wr  = (wid & 3)*32, wn  = (wid >> 2)*32;
    int wr2 = (wid & 1)*32, wn2 = (wid >> 1)*16;

    // ---- init ----
    if (tid < 256){
        s_src[tid] = edge_index[b*512 + tid];
        s_dst[tid] = edge_index[b*512 + 256 + tid];
        s_cedge[tid] = g_csr_edge[b*256 + tid];
        s_sc[tid] = bsc[0];
    }
    if (tid < 128) s_wsc[tid] = Wsc[tid];
    if (tid < 65)  s_coff[tid] = g_csr_off[b*65 + tid];
    if (tid < 128)       s_gv[tid]       = g_gve[b*128 + tid];
    else if (tid < 256)  s_gv[tid]       = g_gvn[b*128 + (tid-128)];
    else if (tid < 384)  s_gv[tid]       = g_gve[(8 + b)*128 + (tid-256)];

    // ee tiles <- g_eenc (256 rows)
    #pragma unroll
    for (int i = tid; i < 4096; i += 512){
        int r = i >> 4, c = i & 15;
        *(uint4*)&s_ee[r*PH + c*8] = *(const uint4*)&g_eenc[((long)b*256 + r)*128 + c*8];
    }
    // h0 = lrelu(A + C + sp*w3 + bias) -> fp16
    #pragma unroll
    for (int i = tid; i < 2048; i += 512){
        int row = i >> 5, c4 = i & 31;
        float sp = spdist[(b*64 + d)*64 + row];
        float4 a  = *(const float4*)&g_A[(b*64 + row)*128 + c4*4];
        float4 cc = *(const float4*)&g_C[bd*128 + c4*4];
        float4 w  = *(const float4*)&w3[c4*4];
        float4 bi = *(const float4*)&bias[c4*4];
        union { uint2 u; __half2 h[2]; } pk;
        pk.h[0] = __floats2half2_rn(lrelu(a.x + cc.x + sp*w.x + bi.x),
                                    lrelu(a.y + cc.y + sp*w.y + bi.y));
        pk.h[1] = __floats2half2_rn(lrelu(a.z + cc.z + sp*w.z + bi.z),
                                    lrelu(a.w + cc.w + sp*w.w + bi.w));
        *(uint2*)&s_h[row*PH + c4*4] = pk.u;
    }

    // fragment addresses
    uint32_t sb = smem_u32(smc);
    int l15 = lane & 15, kA = ((lane>>4)&1)*8, kB = ((lane>>3)&1)*8;
    uint32_t aAe[2][2], aAh[2], aAg[2], aBe[2], aBs, aBs2;
    #pragma unroll
    for (int m = 0; m < 2; m++){
        uint32_t ro = (uint32_t)(((wr + m*16 + l15)*PH + kA))*2u;
        aAe[0][m] = sb + OB_EE + ro;
        aAe[1][m] = sb + OB_EE + 34816u + ro;
        aAh[m] = sb + OB_H  + (uint32_t)(((wr2 + m*16 + l15)*PH + kA))*2u;
        aAg[m] = sb + OB_HS + (uint32_t)(((wr2 + m*16 + l15)*PH + kA))*2u;
    }
    #pragma unroll
    for (int p = 0; p < 2; p++){
        int rn = wn + p*16 + ((lane>>4)<<3) + (lane&7);
        aBe[p] = sb + OB_W + (uint32_t)((rn*PH + kB))*2u;
    }
    {
        int rn = wn2 + ((lane>>4)<<3) + (lane&7);
        aBs  = sb + OB_W  + (uint32_t)((rn*PH + kB))*2u;
        aBs2 = sb + OB_W2 + (uint32_t)((rn*PH + kB))*2u;
    }

    for (int s = 0; s < 2; s++){
        const __half* Wb = g_Wh + (1 + s*5)*16384;
        int gvo = s*256;                         // gve offset
        if (s == 0){
            copy_hh<512>(s_w,  Wb + 1*16384, tid);    // Ws
            copy_hh<512>(s_w2, Wb + 2*16384, tid);    // Wd
        }
        __syncthreads();                         // weights + tiles + h visible

        // ---- hs = h@Ws ; hd = h@Wd ----
        {
            float ch[2][2][4] = {};
            g64h(ch, aAh, aBs);
            #pragma unroll
            for (int m = 0; m < 2; m++){
                int rA = wr2 + m*16 + trow;
                #pragma unroll
                for (int nt = 0; nt < 2; nt++){
                    int col = wn2 + nt*8 + tcol2;
                    *(float2*)&s_hs[rA*PITCH + col]     = make_float2(ch[m][nt][0], ch[m][nt][1]);
                    *(float2*)&s_hs[(rA+8)*PITCH + col] = make_float2(ch[m][nt][2], ch[m][nt][3]);
                }
            }
        }
        {
            float cd[2][2][4] = {};
            g64h(cd, aAh, aBs2);
            #pragma unroll
            for (int m = 0; m < 2; m++){
                int rA = wr2 + m*16 + trow;
                #pragma unroll
                for (int nt = 0; nt < 2; nt++){
                    int col = wn2 + nt*8 + tcol2;
                    *(float2*)&s_hd[rA*PITCH + col]     = make_float2(cd[m][nt][0], cd[m][nt][1]);
                    *(float2*)&s_hd[(rA+8)*PITCH + col] = make_float2(cd[m][nt][2], cd[m][nt][3]);
                }
            }
        }
        __syncthreads();                         // hs/hd visible, s_w/s_w2 reads done
        copy_hh<512>(s_w, Wb, tid);              // Wedge
        if (s == 0) copy_hh<512>(s_w2, Wb + 3*16384, tid);   // Wn1 (for node later)
        __syncthreads();

        // ---- edge tiles (A resident) ----
        for (int et = 0; et < 2; et++){
            int e0 = et*128;
            float c8[2][4][4] = {};
            g128h(c8, aAe[et], aBe);
            if (s == 0){
                __syncthreads();                 // all A-reads of this tile done before in-place write
                #pragma unroll
                for (int m = 0; m < 2; m++){
                    int lrA = wr + m*16 + trow, lrB = lrA + 8;
                    int sA = s_src[e0+lrA], dA = s_dst[e0+lrA];
                    int sB = s_src[e0+lrB], dB = s_dst[e0+lrB];
                    #pragma unroll
                    for (int nt = 0; nt < 4; nt++){
                        int col = wn + nt*8 + tcol2;
                        float2 gv = *(float2*)&s_gv[gvo + col];
                        float2 h1 = *(float2*)&s_hs[sA*PITCH + col];
                        float2 d1 = *(float2*)&s_hd[dA*PITCH + col];
                        float2 p1 = __half22float2(*(__half2*)&s_ee[(e0+lrA)*PH + col]);
                        *(__half2*)&s_ee[(e0+lrA)*PH + col] = __floats2half2_rn(
                            p1.x + lrelu(c8[m][nt][0] + h1.x + d1.x + gv.x),
                            p1.y + lrelu(c8[m][nt][1] + h1.y + d1.y + gv.y));
                        float2 h2 = *(float2*)&s_hs[sB*PITCH + col];
                        float2 d2 = *(float2*)&s_hd[dB*PITCH + col];
                        float2 p2 = __half22float2(*(__half2*)&s_ee[(e0+lrB)*PH + col]);
                        *(__half2*)&s_ee[(e0+lrB)*PH + col] = __floats2half2_rn(
                            p2.x + lrelu(c8[m][nt][2] + h2.x + d2.x + gv.x),
                            p2.y + lrelu(c8[m][nt][3] + h2.y + d2.y + gv.y));
                    }
                }
            } else {
                float part[2][2] = {{0.f,0.f},{0.f,0.f}};
                #pragma unroll
                for (int m = 0; m < 2; m++){
                    int lrA = wr + m*16 + trow, lrB = lrA + 8;
                    int sA = s_src[e0+lrA], dA = s_dst[e0+lrA];
                    int sB = s_src[e0+lrB], dB = s_dst[e0+lrB];
                    #pragma unroll
                    for (int nt = 0; nt < 4; nt++){
                        int col = wn + nt*8 + tcol2;
                        float2 gv = *(float2*)&s_gv[gvo + col];
                        float2 wv = *(float2*)&s_wsc[col];
                        float2 h1 = *(float2*)&s_hs[sA*PITCH + col];
                        float2 d1 = *(float2*)&s_hd[dA*PITCH + col];
                        float2 p1 = __half22float2(*(__half2*)&s_ee[(e0+lrA)*PH + col]);
                        float o1x = p1.x + lrelu(c8[m][nt][0] + h1.x + d1.x + gv.x);
                        float o1y = p1.y + lrelu(c8[m][nt][1] + h1.y + d1.y + gv.y);
                        part[m][0] += o1x*wv.x + o1y*wv.y;
                        float2 h2 = *(float2*)&s_hs[sB*PITCH + col];
                        float2 d2 = *(float2*)&s_hd[dB*PITCH + col];
                        float2 p2 = __half22float2(*(__half2*)&s_ee[(e0+lrB)*PH + col]);
                        float o2x = p2.x + lrelu(c8[m][nt][2] + h2.x + d2.x + gv.x);
                        float o2y = p2.y + lrelu(c8[m][nt][3] + h2.y + d2.y + gv.y);
                        part[m][1] += o2x*wv.x + o2y*wv.y;
                    }
                }
                #pragma unroll
                for (int m = 0; m < 2; m++)
                    #pragma unroll
                    for (int i = 0; i < 2; i++){
                        float v = part[m][i];
                        v += __shfl_xor_sync(0xFFFFFFFFu, v, 1);
                        v += __shfl_xor_sync(0xFFFFFFFFu, v, 2);
                        if ((lane & 3) == 0)
                            atomicAdd(&s_sc[e0 + wr + m*16 + trow + i*8], v);
                    }
            }
        }
        __syncthreads();                         // tiles final / scores done

        if (s == 0){
            // ---- agg from resident ee (CSR) -> s_ag (hs dead) ; Wn2 -> s_w (edge done) ----
            {
                int n = tid >> 3, cg = tid & 7;
                float acc[16];
                #pragma unroll
                for (int q = 0; q < 16; q++) acc[q] = 0.f;
                int j0 = s_coff[n], j1 = s_coff[n+1];
                for (int j = j0; j < j1; j++){
                    const __half2* p = (const __half2*)&s_ee[s_cedge[j]*PH + cg*16];
                    #pragma unroll
                    for (int q = 0; q < 8; q++){
                        float2 v = __half22float2(p[q]);
                        acc[2*q] += v.x; acc[2*q+1] += v.y;
                    }
                }
                union { uint4 u[2]; __half2 h[8]; } pk;
                #pragma unroll
                for (int q = 0; q < 8; q++) pk.h[q] = __floats2half2_rn(acc[2*q], acc[2*q+1]);
                *(uint4*)&s_ag[n*PH + cg*16]     = pk.u[0];
                *(uint4*)&s_ag[n*PH + cg*16 + 8] = pk.u[1];
            }
            copy_hh<512>(s_w, Wb + 4*16384, tid);      // Wn2
            __syncthreads();

            float cn[2][2][4] = {};
            g64h(cn, aAh, aBs2);                 // h @ Wn1 (s_w2)
            g64h(cn, aAg, aBs);                  // agg @ Wn2 (s_w)
            __syncthreads();                     // all s_h reads done
            #pragma unroll
            for (int m = 0; m < 2; m++){
                int rA = wr2 + m*16 + trow;
                #pragma unroll
                for (int nt = 0; nt < 2; nt++){
                    int col = wn2 + nt*8 + tcol2;
                    float2 gv = *(float2*)&s_gv[128 + col];
                    float2 h1 = __half22float2(*(__half2*)&s_h[rA*PH + col]);
                    float2 h2 = __half22float2(*(__half2*)&s_h[(rA+8)*PH + col]);
                    *(__half2*)&s_h[rA*PH + col] = __floats2half2_rn(
                        h1.x + lrelu(cn[m][nt][0] + gv.x),
                        h1.y + lrelu(cn[m][nt][1] + gv.y));
                    *(__half2*)&s_h[(rA+8)*PH + col] = __floats2half2_rn(
                        h2.x + lrelu(cn[m][nt][2] + gv.x),
                        h2.y + lrelu(cn[m][nt][3] + gv.y));
                }
            }
            __syncthreads();                     // s_h final; s_w/s_w2 free
            copy_hh<512>(s_w,  g_Wh + (1 + 5)*16384 + 1*16384, tid);   // Ws (s1)
            copy_hh<512>(s_w2, g_Wh + (1 + 5)*16384 + 2*16384, tid);   // Wd (s1)
        } else {
            if (tid < 256)
                out[b*(E_*N_) + tid*N_ + d] = s_sc[tid];
        }
    }
}

// ---------------- launch ----------------
extern "C" void kernel_launch(void* const* d_in, const int* in_sizes, int n_in,
                              void* d_out, int out_size){
    const float* x          = (const float*)d_in[0];
    const float* edge_attr  = (const float*)d_in[1];
    const float* u          = (const float*)d_in[2];
    const float* spdist     = (const float*)d_in[3];
    const int*   edge_index = (const int*)  d_in[4];
    const float* W_node_enc = (const float*)d_in[5];
    const float* b_node_enc = (const float*)d_in[6];
    const float* W_edge_enc = (const float*)d_in[7];
    const float* b_edge_enc = (const float*)d_in[8];
    const float* W_glob_enc = (const float*)d_in[9];
    const float* b_glob_enc = (const float*)d_in[10];
    const float* W_edge_upd = (const float*)d_in[11];
    const float* b_edge_upd = (const float*)d_in[12];
    const float* W_node_upd = (const float*)d_in[13];
    const float* b_node_upd = (const float*)d_in[14];
    const float* W_score    = (const float*)d_in[15];
    const float* b_score    = (const float*)d_in[16];
    float* out = (float*)d_out;

    cudaFuncSetAttribute(k_prep,  cudaFuncAttributeMaxDynamicSharedMemorySize, SMEM_PREP);
    cudaFuncSetAttribute(k_fused, cudaFuncAttributeMaxDynamicSharedMemorySize, SMEM_FUSED);

    k_prep <<<142, 256, SMEM_PREP>>>(x, W_node_enc, u, W_glob_enc, b_glob_enc,
                                     W_edge_enc, b_edge_enc, edge_attr,
                                     W_edge_upd, b_edge_upd, W_node_upd, b_node_upd,
                                     edge_index);
    k_fused<<<512, 512, SMEM_FUSED>>>(spdist, edge_index,
                                      W_node_enc + 256*128, b_node_enc,
                                      W_score, b_score, out);
}

// round 11
// speedup vs baseline: 2.2740x; 1.1489x over previous
#include <cuda_runtime.h>
#include <cuda_fp16.h>
#include <cstdint>

#define B_   8
#define N_   64
#define E_   256
#define L_   128
#define PH    136      // half pitch for MMA operand tiles

// ---------------- device globals ----------------
__device__ float  g_A[512*128];
__device__ float  g_C[512*128];
__device__ __half g_eenc[2048*128];
__device__ float  g_gve[2*8*128];
__device__ float  g_gvn[2*8*128];
__device__ __half g_Wh[11*128*128];       // pre-transposed [n][k] fp16 weights
__device__ int    g_csr_off[8*65];
__device__ int    g_csr_edge[8*256];

__device__ __forceinline__ float lrelu(float v){ return v > 0.f ? v : 0.01f*v; }
__device__ __forceinline__ uint32_t smem_u32(const void* p){
    uint32_t a;
    asm("{ .reg .u64 t; cvta.to.shared.u64 t, %1; cvt.u32.u64 %0, t; }" : "=r"(a) : "l"(p));
    return a;
}

#define LDSM4(D, addr) \
    asm volatile("ldmatrix.sync.aligned.m8n8.x4.shared.b16 {%0,%1,%2,%3}, [%4];" \
        : "=r"((D)[0]),"=r"((D)[1]),"=r"((D)[2]),"=r"((D)[3]) : "r"(addr))

#define MMA_H(C, A, b0, b1) \
    asm volatile("mma.sync.aligned.m16n8k16.row.col.f32.f16.f16.f32 " \
        "{%0,%1,%2,%3}, {%4,%5,%6,%7}, {%8,%9}, {%0,%1,%2,%3};" \
        : "+f"((C)[0]),"+f"((C)[1]),"+f"((C)[2]),"+f"((C)[3]) \
        : "r"((A)[0]),"r"((A)[1]),"r"((A)[2]),"r"((A)[3]), "r"(b0),"r"(b1))

// ---------------- tile copies ----------------
template<int NT>
__device__ __forceinline__ void copy_hh(__half* dst, const __half* __restrict__ src, int tid){
    #pragma unroll
    for (int i = tid; i < 2048; i += NT){
        int r = i >> 4, c = i & 15;
        *(uint4*)&dst[r*PH + c*8] = *(const uint4*)&src[r*128 + c*8];
    }
}
template<int NT>
__device__ __forceinline__ void copy_f2h(__half* dst, const float* __restrict__ src, int tid){
    #pragma unroll
    for (int i = tid; i < 2048; i += NT){
        int r = i >> 4, c = i & 15;
        float4 v0 = *(const float4*)&src[r*128 + c*8];
        float4 v1 = *(const float4*)&src[r*128 + c*8 + 4];
        union { uint4 u; __half2 h[4]; } pk;
        pk.h[0] = __floats2half2_rn(v0.x, v0.y);
        pk.h[1] = __floats2half2_rn(v0.z, v0.w);
        pk.h[2] = __floats2half2_rn(v1.x, v1.y);
        pk.h[3] = __floats2half2_rn(v1.z, v1.w);
        *(uint4*)&dst[r*PH + c*8] = pk.u;
    }
}

// ---------------- gemm cores ----------------
// 128x128xK128, 16 warps (warp 32m x 32n)
__device__ __forceinline__ void g128h(float c[2][4][4], const uint32_t aA[2], const uint32_t aB[2]){
    #pragma unroll
    for (int k = 0; k < 8; k++){
        uint32_t A0[4], A1[4];
        LDSM4(A0, aA[0] + (uint32_t)k*32u);
        LDSM4(A1, aA[1] + (uint32_t)k*32u);
        #pragma unroll
        for (int p = 0; p < 2; p++){
            uint32_t Bv[4];
            LDSM4(Bv, aB[p] + (uint32_t)k*32u);
            MMA_H(c[0][2*p],   A0, Bv[0], Bv[1]);
            MMA_H(c[0][2*p+1], A0, Bv[2], Bv[3]);
            MMA_H(c[1][2*p],   A1, Bv[0], Bv[1]);
            MMA_H(c[1][2*p+1], A1, Bv[2], Bv[3]);
        }
    }
}
// 64x128xK128, 16 warps (warp 32m x 16n)
__device__ __forceinline__ void g64h(float c[2][2][4], const uint32_t aA[2], uint32_t aB){
    #pragma unroll
    for (int k = 0; k < 8; k++){
        uint32_t A0[4], A1[4], Bv[4];
        LDSM4(A0, aA[0] + (uint32_t)k*32u);
        LDSM4(A1, aA[1] + (uint32_t)k*32u);
        LDSM4(Bv, aB + (uint32_t)k*32u);
        MMA_H(c[0][0], A0, Bv[0], Bv[1]);
        MMA_H(c[0][1], A0, Bv[2], Bv[3]);
        MMA_H(c[1][0], A1, Bv[0], Bv[1]);
        MMA_H(c[1][1], A1, Bv[2], Bv[3]);
    }
}
// dual 64x128 gemm sharing A fragments (hs and hd)
__device__ __forceinline__ void g64h_dual(float ch[2][2][4], float cd[2][2][4],
                                          const uint32_t aA[2], uint32_t aB, uint32_t aB2){
    #pragma unroll
    for (int k = 0; k < 8; k++){
        uint32_t A0[4], A1[4], Bv[4], Bw[4];
        LDSM4(A0, aA[0] + (uint32_t)k*32u);
        LDSM4(A1, aA[1] + (uint32_t)k*32u);
        LDSM4(Bv, aB + (uint32_t)k*32u);
        LDSM4(Bw, aB2 + (uint32_t)k*32u);
        MMA_H(ch[0][0], A0, Bv[0], Bv[1]);
        MMA_H(ch[0][1], A0, Bv[2], Bv[3]);
        MMA_H(ch[1][0], A1, Bv[0], Bv[1]);
        MMA_H(ch[1][1], A1, Bv[2], Bv[3]);
        MMA_H(cd[0][0], A0, Bw[0], Bw[1]);
        MMA_H(cd[0][1], A0, Bw[2], Bw[3]);
        MMA_H(cd[1][0], A1, Bw[0], Bw[1]);
        MMA_H(cd[1][1], A1, Bw[2], Bw[3]);
    }
}
// 128x128xK128, 8 warps (warp 32m x 64n) — for eenc blocks
__device__ __forceinline__ void g128h8(float c[2][8][4], const uint32_t aA[2], const uint32_t aB[4]){
    #pragma unroll
    for (int k = 0; k < 8; k++){
        uint32_t A0[4], A1[4];
        LDSM4(A0, aA[0] + (uint32_t)k*32u);
        LDSM4(A1, aA[1] + (uint32_t)k*32u);
        #pragma unroll
        for (int p = 0; p < 4; p++){
            uint32_t Bv[4];
            LDSM4(Bv, aB[p] + (uint32_t)k*32u);
            MMA_H(c[0][2*p],   A0, Bv[0], Bv[1]);
            MMA_H(c[0][2*p+1], A0, Bv[2], Bv[3]);
            MMA_H(c[1][2*p],   A1, Bv[0], Bv[1]);
            MMA_H(c[1][2*p+1], A1, Bv[2], Bv[3]);
        }
    }
}

// ---------------- merged prep kernel (256 threads) ----------------
#define SMEM_PREP (34816*2)
__global__ void k_prep(const float* __restrict__ x, const float* __restrict__ Wne,
                       const float* __restrict__ u, const float* __restrict__ Wg,
                       const float* __restrict__ bg,
                       const float* __restrict__ Wenc, const float* __restrict__ benc,
                       const float* __restrict__ ea,
                       const float* __restrict__ Wedge, const float* __restrict__ be,
                       const float* __restrict__ Wnode, const float* __restrict__ bn,
                       const int* __restrict__ edge_index){
    __shared__ float sbuf[64*129];
    extern __shared__ char dyn[];
    int blk = blockIdx.x, tid = threadIdx.x;
    if (blk < 22){
        int mat = blk >> 1, k0 = (blk & 1)*64;
        int m = mat - 1, s = m / 5, t = m % 5;
        #pragma unroll
        for (int i = tid; i < 8192; i += 256){
            int kk = i >> 7, n = i & 127;
            int k = k0 + kk;
            float v;
            if (mat == 0) v = Wenc[k*L_ + n];
            else if (t == 0) v = Wedge[(s*512 +       k)*L_ + n];
            else if (t == 1) v = Wedge[(s*512 + 128 + k)*L_ + n];
            else if (t == 2) v = Wedge[(s*512 + 256 + k)*L_ + n];
            else if (t == 3) v = Wnode[(s*384 +       k)*L_ + n];
            else             v = Wnode[(s*384 + 128 + k)*L_ + n];
            sbuf[kk*129 + n] = v;
        }
        __syncthreads();
        #pragma unroll
        for (int j = tid; j < 8192; j += 256){
            int n = j >> 6, kk = j & 63;
            g_Wh[mat*16384 + n*128 + k0 + kk] = __float2half_rn(sbuf[kk*129 + n]);
        }
    } else if (blk < 86){
        float (*xs)[128] = (float(*)[128])sbuf;
        const float* W1 = Wne;
        const float* W2 = Wne + 16384;
        int r0 = (blk - 22)*8;
        for (int i = tid; i < 1024; i += 256) xs[i>>7][i&127] = x[(r0 + (i>>7))*128 + (i&127)];
        __syncthreads();
        int c = tid & 127, rq = tid >> 7;
        float a1[4] = {0,0,0,0}, a2[4] = {0,0,0,0};
        #pragma unroll 8
        for (int k = 0; k < 128; k++){
            float w1 = W1[k*128 + c], w2 = W2[k*128 + c];
            #pragma unroll
            for (int j = 0; j < 4; j++){
                float xv = xs[rq*4 + j][k];
                a1[j] += xv*w1; a2[j] += xv*w2;
            }
        }
        #pragma unroll
        for (int j = 0; j < 4; j++){
            g_A[(r0 + rq*4 + j)*128 + c] = a1[j];
            g_C[(r0 + rq*4 + j)*128 + c] = a2[j];
        }
    } else if (blk < 94){
        int* cnt = (int*)sbuf;
        int* off = cnt + 64;
        int b = blk - 86;
        if (tid < 64) cnt[tid] = 0;
        __syncthreads();
        int dv = edge_index[b*512 + 256 + tid];
        atomicAdd(&cnt[dv], 1);
        __syncthreads();
        if (tid == 0){
            int o = 0;
            for (int n = 0; n < 64; n++){ off[n] = o; o += cnt[n]; }
            off[64] = o;
            for (int n = 0; n <= 64; n++) g_csr_off[b*65 + n] = off[n];
            for (int n = 0; n < 64; n++) cnt[n] = off[n];
        }
        __syncthreads();
        int pos = atomicAdd(&cnt[dv], 1);
        g_csr_edge[b*256 + pos] = tid;
    } else if (blk < 126){
        float* red = sbuf;
        float* sgg = sbuf + 256;
        int id = blk - 94;
        int b = id & 7, s = (id >> 3) & 1, kind = id >> 4;
        int c = tid & 127, hf = tid >> 7;
        float p = 0.f;
        #pragma unroll 16
        for (int k = 0; k < 64; k++)
            p += u[b*128 + hf*64 + k] * Wg[(hf*64 + k)*128 + c];
        red[tid] = p;
        __syncthreads();
        if (tid < 128) sgg[tid] = lrelu(bg[tid] + red[tid] + red[tid + 128]);
        __syncthreads();
        const float* W = (kind == 0) ? (Wedge + (s*512 + 384)*L_)
                                     : (Wnode + (s*384 + 256)*L_);
        float q = 0.f;
        #pragma unroll 16
        for (int k = 0; k < 64; k++)
            q += sgg[hf*64 + k] * W[(hf*64 + k)*128 + c];
        red[tid] = q;
        __syncthreads();
        if (tid < 128){
            float acc = ((kind == 0) ? be[s*128 + tid] : bn[s*128 + tid])
                      + red[tid] + red[tid + 128];
            if (kind == 0) g_gve[(s*8 + b)*128 + tid] = acc;
            else           g_gvn[(s*8 + b)*128 + tid] = acc;
        }
    } else {
        __half* s_xh = (__half*)dyn;
        __half* s_wh = (__half*)(dyn + 34816);
        int eb = blk - 126;
        int row0 = eb*128;
        int wid = tid >> 5, lane = tid & 31;
        int trow = lane >> 2, tcol2 = (lane & 3)*2;
        int wr = (wid & 3)*32, wn = (wid >> 2)*64;

        copy_f2h<256>(s_xh, ea + (long)row0*128, tid);
        #pragma unroll
        for (int i = tid; i < 16384; i += 256){
            int k = i >> 7, n = i & 127;
            s_wh[n*PH + k] = __float2half_rn(Wenc[k*128 + n]);
        }
        __syncthreads();

        uint32_t sb = smem_u32(dyn);
        int l15 = lane & 15, kA = ((lane>>4)&1)*8, kB = ((lane>>3)&1)*8;
        uint32_t aA[2], aB[4];
        #pragma unroll
        for (int m = 0; m < 2; m++)
            aA[m] = sb + (uint32_t)(((wr + m*16 + l15)*PH + kA))*2u;
        #pragma unroll
        for (int p = 0; p < 4; p++){
            int rn = wn + p*16 + ((lane>>4)<<3) + (lane&7);
            aB[p] = sb + 34816u + (uint32_t)((rn*PH + kB))*2u;
        }
        float c8[2][8][4] = {};
        g128h8(c8, aA, aB);

        #pragma unroll
        for (int m = 0; m < 2; m++){
            int rA = row0 + wr + m*16 + trow;
            #pragma unroll
            for (int nt = 0; nt < 8; nt++){
                int col = wn + nt*8 + tcol2;
                float2 bi = *(const float2*)&benc[col];
                *(__half2*)&g_eenc[(long)rA*128 + col] =
                    __floats2half2_rn(lrelu(c8[m][nt][0]+bi.x), lrelu(c8[m][nt][1]+bi.y));
                *(__half2*)&g_eenc[(long)(rA+8)*128 + col] =
                    __floats2half2_rn(lrelu(c8[m][nt][2]+bi.x), lrelu(c8[m][nt][3]+bi.y));
            }
        }
    }
}

// ---------------- fused per-(b,d) kernel ----------------
#define OB_EE  0         // 256 x PH fp16 = 69632
#define OB_W   69632     // 34816
#define OB_W2  104448    // 34816
#define OB_H   139264    // 17408
#define OB_HS  156672    // 17408 fp16 (s_ag aliases)
#define OB_HD  174080    // 17408 fp16
#define OB_GV  191488    // 2048
#define OB_WSC 193536    // 512
#define OB_SC  194048    // 1024
#define OB_INT 195072    // 3336
#define SMEM_FUSED 198408

__global__ __launch_bounds__(512, 1) void k_fused(
    const float* __restrict__ spdist, const int* __restrict__ edge_index,
    const float* __restrict__ w3, const float* __restrict__ bias,
    const float* __restrict__ Wsc, const float* __restrict__ bsc,
    float* __restrict__ out)
{
    extern __shared__ char smc[];
    __half* s_ee  = (__half*)(smc + OB_EE);
    __half* s_h   = (__half*)(smc + OB_H);
    __half* s_hs  = (__half*)(smc + OB_HS);
    __half* s_hd  = (__half*)(smc + OB_HD);
    __half* s_ag  = (__half*)(smc + OB_HS);     // aliases s_hs (hs dead by then)
    float*  s_gv  = (float*)(smc + OB_GV);
    float*  s_wsc = (float*)(smc + OB_WSC);
    float*  s_sc  = (float*)(smc + OB_SC);
    int*    s_src = (int*)(smc + OB_INT);
    int*    s_dst = s_src + 256;
    int*    s_coff = s_dst + 256;
    int*    s_cedge = s_coff + 66;
    __half* s_w   = (__half*)(smc + OB_W);
    __half* s_w2  = (__half*)(smc + OB_W2);

    int tid = threadIdx.x, wid = tid >> 5, lane = tid & 31;
    int bd = blockIdx.x, b = bd >> 6, d = bd & 63;
    int trow = lane >> 2, tcol2 = (lane & 3)*2;
    int wr  = (wid & 3)*32, wn  = (wid >> 2)*32;
    int wr2 = (wid & 1)*32, wn2 = (wid >> 1)*16;

    // ---- init ----
    if (tid < 256){
        s_src[tid] = edge_index[b*512 + tid];
        s_dst[tid] = edge_index[b*512 + 256 + tid];
        s_cedge[tid] = g_csr_edge[b*256 + tid];
        s_sc[tid] = bsc[0];
    }
    if (tid < 128) s_wsc[tid] = Wsc[tid];
    if (tid < 65)  s_coff[tid] = g_csr_off[b*65 + tid];
    if (tid < 128)       s_gv[tid] = g_gve[b*128 + tid];
    else if (tid < 256)  s_gv[tid] = g_gvn[b*128 + (tid-128)];
    else if (tid < 384)  s_gv[tid] = g_gve[(8 + b)*128 + (tid-256)];

    // ee tiles <- g_eenc
    #pragma unroll
    for (int i = tid; i < 4096; i += 512){
        int r = i >> 4, c = i & 15;
        *(uint4*)&s_ee[r*PH + c*8] = *(const uint4*)&g_eenc[((long)b*256 + r)*128 + c*8];
    }
    // h0 = lrelu(A + C + sp*w3 + bias) -> fp16
    #pragma unroll
    for (int i = tid; i < 2048; i += 512){
        int row = i >> 5, c4 = i & 31;
        float sp = spdist[(b*64 + d)*64 + row];
        float4 a  = *(const float4*)&g_A[(b*64 + row)*128 + c4*4];
        float4 cc = *(const float4*)&g_C[bd*128 + c4*4];
        float4 w  = *(const float4*)&w3[c4*4];
        float4 bi = *(const float4*)&bias[c4*4];
        union { uint2 u; __half2 h[2]; } pk;
        pk.h[0] = __floats2half2_rn(lrelu(a.x + cc.x + sp*w.x + bi.x),
                                    lrelu(a.y + cc.y + sp*w.y + bi.y));
        pk.h[1] = __floats2half2_rn(lrelu(a.z + cc.z + sp*w.z + bi.z),
                                    lrelu(a.w + cc.w + sp*w.w + bi.w));
        *(uint2*)&s_h[row*PH + c4*4] = pk.u;
    }

    // fragment addresses
    uint32_t sb = smem_u32(smc);
    int l15 = lane & 15, kA = ((lane>>4)&1)*8, kB = ((lane>>3)&1)*8;
    uint32_t aAe[2][2], aAh[2], aAg[2], aBe[2], aBs, aBs2;
    #pragma unroll
    for (int m = 0; m < 2; m++){
        uint32_t ro = (uint32_t)(((wr + m*16 + l15)*PH + kA))*2u;
        aAe[0][m] = sb + OB_EE + ro;
        aAe[1][m] = sb + OB_EE + 34816u + ro;
        aAh[m] = sb + OB_H  + (uint32_t)(((wr2 + m*16 + l15)*PH + kA))*2u;
        aAg[m] = sb + OB_HS + (uint32_t)(((wr2 + m*16 + l15)*PH + kA))*2u;
    }
    #pragma unroll
    for (int p = 0; p < 2; p++){
        int rn = wn + p*16 + ((lane>>4)<<3) + (lane&7);
        aBe[p] = sb + OB_W + (uint32_t)((rn*PH + kB))*2u;
    }
    {
        int rn = wn2 + ((lane>>4)<<3) + (lane&7);
        aBs  = sb + OB_W  + (uint32_t)((rn*PH + kB))*2u;
        aBs2 = sb + OB_W2 + (uint32_t)((rn*PH + kB))*2u;
    }

    for (int s = 0; s < 2; s++){
        const __half* Wb = g_Wh + (1 + s*5)*16384;
        int gvo = s*256;
        if (s == 0){
            copy_hh<512>(s_w,  Wb + 1*16384, tid);    // Ws
            copy_hh<512>(s_w2, Wb + 2*16384, tid);    // Wd
        }
        __syncthreads();

        // ---- hs/hd dual gemm (shared A frags), fp16 stores ----
        {
            float ch[2][2][4] = {}, cd[2][2][4] = {};
            g64h_dual(ch, cd, aAh, aBs, aBs2);
            #pragma unroll
            for (int m = 0; m < 2; m++){
                int rA = wr2 + m*16 + trow;
                #pragma unroll
                for (int nt = 0; nt < 2; nt++){
                    int col = wn2 + nt*8 + tcol2;
                    *(__half2*)&s_hs[rA*PH + col]     = __floats2half2_rn(ch[m][nt][0], ch[m][nt][1]);
                    *(__half2*)&s_hs[(rA+8)*PH + col] = __floats2half2_rn(ch[m][nt][2], ch[m][nt][3]);
                    *(__half2*)&s_hd[rA*PH + col]     = __floats2half2_rn(cd[m][nt][0], cd[m][nt][1]);
                    *(__half2*)&s_hd[(rA+8)*PH + col] = __floats2half2_rn(cd[m][nt][2], cd[m][nt][3]);
                }
            }
        }
        __syncthreads();                         // hs/hd visible; s_w/s_w2 reads done
        copy_hh<512>(s_w, Wb, tid);              // Wedge
        if (s == 0) copy_hh<512>(s_w2, Wb + 3*16384, tid);   // Wn1
        __syncthreads();

        // ---- edge tiles ----
        for (int et = 0; et < 2; et++){
            int e0 = et*128;
            float c8[2][4][4] = {};
            g128h(c8, aAe[et], aBe);
            if (s == 0){
                __syncthreads();                 // A-reads done before in-place write
                #pragma unroll
                for (int m = 0; m < 2; m++){
                    int lrA = wr + m*16 + trow, lrB = lrA + 8;
                    int sA = s_src[e0+lrA], dA = s_dst[e0+lrA];
                    int sB = s_src[e0+lrB], dB = s_dst[e0+lrB];
                    #pragma unroll
                    for (int nt = 0; nt < 4; nt++){
                        int col = wn + nt*8 + tcol2;
                        float2 gv = *(float2*)&s_gv[gvo + col];
                        float2 h1 = __half22float2(*(__half2*)&s_hs[sA*PH + col]);
                        float2 d1 = __half22float2(*(__half2*)&s_hd[dA*PH + col]);
                        float2 p1 = __half22float2(*(__half2*)&s_ee[(e0+lrA)*PH + col]);
                        *(__half2*)&s_ee[(e0+lrA)*PH + col] = __floats2half2_rn(
                            p1.x + lrelu(c8[m][nt][0] + h1.x + d1.x + gv.x),
                            p1.y + lrelu(c8[m][nt][1] + h1.y + d1.y + gv.y));
                        float2 h2 = __half22float2(*(__half2*)&s_hs[sB*PH + col]);
                        float2 d2 = __half22float2(*(__half2*)&s_hd[dB*PH + col]);
                        float2 p2 = __half22float2(*(__half2*)&s_ee[(e0+lrB)*PH + col]);
                        *(__half2*)&s_ee[(e0+lrB)*PH + col] = __floats2half2_rn(
                            p2.x + lrelu(c8[m][nt][2] + h2.x + d2.x + gv.x),
                            p2.y + lrelu(c8[m][nt][3] + h2.y + d2.y + gv.y));
                    }
                }
            } else {
                float part[2][2] = {{0.f,0.f},{0.f,0.f}};
                #pragma unroll
                for (int m = 0; m < 2; m++){
                    int lrA = wr + m*16 + trow, lrB = lrA + 8;
                    int sA = s_src[e0+lrA], dA = s_dst[e0+lrA];
                    int sB = s_src[e0+lrB], dB = s_dst[e0+lrB];
                    #pragma unroll
                    for (int nt = 0; nt < 4; nt++){
                        int col = wn + nt*8 + tcol2;
                        float2 gv = *(float2*)&s_gv[gvo + col];
                        float2 wv = *(float2*)&s_wsc[col];
                        float2 h1 = __half22float2(*(__half2*)&s_hs[sA*PH + col]);
                        float2 d1 = __half22float2(*(__half2*)&s_hd[dA*PH + col]);
                        float2 p1 = __half22float2(*(__half2*)&s_ee[(e0+lrA)*PH + col]);
                        float o1x = p1.x + lrelu(c8[m][nt][0] + h1.x + d1.x + gv.x);
                        float o1y = p1.y + lrelu(c8[m][nt][1] + h1.y + d1.y + gv.y);
                        part[m][0] += o1x*wv.x + o1y*wv.y;
                        float2 h2 = __half22float2(*(__half2*)&s_hs[sB*PH + col]);
                        float2 d2 = __half22float2(*(__half2*)&s_hd[dB*PH + col]);
                        float2 p2 = __half22float2(*(__half2*)&s_ee[(e0+lrB)*PH + col]);
                        float o2x = p2.x + lrelu(c8[m][nt][2] + h2.x + d2.x + gv.x);
                        float o2y = p2.y + lrelu(c8[m][nt][3] + h2.y + d2.y + gv.y);
                        part[m][1] += o2x*wv.x + o2y*wv.y;
                    }
                }
                #pragma unroll
                for (int m = 0; m < 2; m++)
                    #pragma unroll
                    for (int i = 0; i < 2; i++){
                        float v = part[m][i];
                        v += __shfl_xor_sync(0xFFFFFFFFu, v, 1);
                        v += __shfl_xor_sync(0xFFFFFFFFu, v, 2);
                        if ((lane & 3) == 0)
                            atomicAdd(&s_sc[e0 + wr + m*16 + trow + i*8], v);
                    }
            }
        }
        __syncthreads();

        if (s == 0){
            // ---- agg (uint4 loads) -> s_ag ; Wn2 -> s_w ----
            {
                int n = tid >> 3, cg = tid & 7;
                float acc[16];
                #pragma unroll
                for (int q = 0; q < 16; q++) acc[q] = 0.f;
                int j0 = s_coff[n], j1 = s_coff[n+1];
                for (int j = j0; j < j1; j++){
                    const uint4* p = (const uint4*)&s_ee[s_cedge[j]*PH + cg*16];
                    uint4 v0 = p[0], v1 = p[1];
                    const __half2* h0 = (const __half2*)&v0;
                    const __half2* h1 = (const __half2*)&v1;
                    #pragma unroll
                    for (int q = 0; q < 4; q++){
                        float2 a0 = __half22float2(h0[q]);
                        float2 a1 = __half22float2(h1[q]);
                        acc[2*q]   += a0.x; acc[2*q+1] += a0.y;
                        acc[8+2*q] += a1.x; acc[8+2*q+1] += a1.y;
                    }
                }
                union { uint4 u[2]; __half2 h[8]; } pk;
                #pragma unroll
                for (int q = 0; q < 8; q++) pk.h[q] = __floats2half2_rn(acc[2*q], acc[2*q+1]);
                *(uint4*)&s_ag[n*PH + cg*16]     = pk.u[0];
                *(uint4*)&s_ag[n*PH + cg*16 + 8] = pk.u[1];
            }
            copy_hh<512>(s_w, Wb + 4*16384, tid);      // Wn2
            __syncthreads();

            float cn[2][2][4] = {};
            g64h(cn, aAh, aBs2);                 // h @ Wn1 (s_w2)
            g64h(cn, aAg, aBs);                  // agg @ Wn2 (s_w)
            __syncthreads();
            #pragma unroll
            for (int m = 0; m < 2; m++){
                int rA = wr2 + m*16 + trow;
                #pragma unroll
                for (int nt = 0; nt < 2; nt++){
                    int col = wn2 + nt*8 + tcol2;
                    float2 gv = *(float2*)&s_gv[128 + col];
                    float2 h1 = __half22float2(*(__half2*)&s_h[rA*PH + col]);
                    float2 h2 = __half22float2(*(__half2*)&s_h[(rA+8)*PH + col]);
                    *(__half2*)&s_h[rA*PH + col] = __floats2half2_rn(
                        h1.x + lrelu(cn[m][nt][0] + gv.x),
                        h1.y + lrelu(cn[m][nt][1] + gv.y));
                    *(__half2*)&s_h[(rA+8)*PH + col] = __floats2half2_rn(
                        h2.x + lrelu(cn[m][nt][2] + gv.x),
                        h2.y + lrelu(cn[m][nt][3] + gv.y));
                }
            }
            __syncthreads();
            copy_hh<512>(s_w,  g_Wh + 6*16384 + 1*16384, tid);   // Ws (s1)
            copy_hh<512>(s_w2, g_Wh + 6*16384 + 2*16384, tid);   // Wd (s1)
        } else {
            if (tid < 256)
                out[b*(E_*N_) + tid*N_ + d] = s_sc[tid];
        }
    }
}

// ---------------- launch ----------------
extern "C" void kernel_launch(void* const* d_in, const int* in_sizes, int n_in,
                              void* d_out, int out_size){
    const float* x          = (const float*)d_in[0];
    const float* edge_attr  = (const float*)d_in[1];
    const float* u          = (const float*)d_in[2];
    const float* spdist     = (const float*)d_in[3];
    const int*   edge_index = (const int*)  d_in[4];
    const float* W_node_enc = (const float*)d_in[5];
    const float* b_node_enc = (const float*)d_in[6];
    const float* W_edge_enc = (const float*)d_in[7];
    const float* b_edge_enc = (const float*)d_in[8];
    const float* W_glob_enc = (const float*)d_in[9];
    const float* b_glob_enc = (const float*)d_in[10];
    const float* W_edge_upd = (const float*)d_in[11];
    const float* b_edge_upd = (const float*)d_in[12];
    const float* W_node_upd = (const float*)d_in[13];
    const float* b_node_upd = (const float*)d_in[14];
    const float* W_score    = (const float*)d_in[15];
    const float* b_score    = (const float*)d_in[16];
    float* out = (float*)d_out;

    cudaFuncSetAttribute(k_prep,  cudaFuncAttributeMaxDynamicSharedMemorySize, SMEM_PREP);
    cudaFuncSetAttribute(k_fused, cudaFuncAttributeMaxDynamicSharedMemorySize, SMEM_FUSED);

    k_prep <<<142, 256, SMEM_PREP>>>(x, W_node_enc, u, W_glob_enc, b_glob_enc,
                                     W_edge_enc, b_edge_enc, edge_attr,
                                     W_edge_upd, b_edge_upd, W_node_upd, b_node_upd,
                                     edge_index);
    k_fused<<<512, 512, SMEM_FUSED>>>(spdist, edge_index,
                                      W_node_enc + 256*128, b_node_enc,
                                      W_score, b_score, out);
}